// round 4
// baseline (speedup 1.0000x reference)
#include <cuda_runtime.h>
#include <math.h>

#define BATCH 4096
#define CELLS 1024
#define KSTRIDE (BATCH*CELLS)   // 4194304 elements per (k) slab

// ---------------- device global scratch (no allocations allowed) ----------------
__device__ float g_Mempty[CELLS*CELLS];
__device__ float g_Meach [CELLS*CELLS];
__device__ float g_Mnot  [CELLS*CELLS];
__device__ float g_Mnot2 [CELLS*CELLS];

__device__ float g_emptyA[KSTRIDE];
__device__ float g_eachA [4*KSTRIDE];
__device__ float g_E     [KSTRIDE];
__device__ float g_Aea   [4*KSTRIDE];
__device__ float g_P     [4*KSTRIDE];
__device__ float g_N     [4*KSTRIDE];
__device__ float g_X     [4*KSTRIDE];
__device__ float g_D     [4*KSTRIDE];
__device__ float g_a     [KSTRIDE];
__device__ float g_s     [KSTRIDE];
__device__ unsigned char g_cls[KSTRIDE];
__device__ float g_x1[BATCH*100];
__device__ float g_x2[BATCH*100];

// ---------------- build conv matrices: M[i=(v,h)][o=(y,x)] = w[v-y+16][h-x+16] ----------------
__global__ void build_M_k(const float* __restrict__ w_each,
                          const float* __restrict__ w_not,
                          const float* __restrict__ w_not2,
                          const float* __restrict__ w_empty) {
    int idx = blockIdx.x * blockDim.x + threadIdx.x;
    if (idx >= CELLS*CELLS) return;
    int i = idx >> 10;      // input cell
    int o = idx & 1023;     // output cell
    int v = i >> 5, h = i & 31;
    int y = o >> 5, x = o & 31;
    int dy = v - y + 16, dx = h - x + 16;
    float we = 0.f, wa = 0.f, wn = 0.f, w2 = 0.f;
    if ((unsigned)dy < 33u && (unsigned)dx < 33u) {
        int wi = dy * 33 + dx;
        we = w_empty[wi]; wa = w_each[wi]; wn = w_not[wi]; w2 = w_not2[wi];
    }
    g_Mempty[idx] = we;
    g_Meach [idx] = wa;
    g_Mnot  [idx] = wn;
    g_Mnot2 [idx] = w2;
}

// ---------------- masks ----------------
__global__ void build_masks_k(const int* __restrict__ dots) {
    int idx = blockIdx.x * blockDim.x + threadIdx.x;
    if (idx >= KSTRIDE) return;
    int b = idx >> 10;
    int i = idx & 1023;
    int c = dots[i * BATCH + b];   // dots[(v*32+h)*B + b]
    g_cls[idx] = (unsigned char)c;
    g_emptyA[idx] = (c == 0) ? 1.f : 0.f;
#pragma unroll
    for (int k = 0; k < 4; k++)
        g_eachA[k*KSTRIDE + idx] = (c == k + 1) ? 1.f : 0.f;
}

// ---------------- fp32 SGEMM: C[Mrows x 1024] = A[Mrows x 1024] @ Bm[1024 x 1024] ----------------
// 128x128 block tile, K-tile 8, 256 threads, 8x8 per thread, double-buffered smem.
__global__ __launch_bounds__(256, 2)
void sgemm_k(int sel, int Mrows) {
    const float* A; const float* Bm; float* C;
    switch (sel) {
        case 0:  A = g_emptyA; Bm = g_Mempty; C = g_E;   break;
        case 1:  A = g_eachA;  Bm = g_Meach;  C = g_Aea; break;
        case 2:  A = g_eachA;  Bm = g_Mnot;   C = g_P;   break;
        default: A = g_X;      Bm = g_Mnot2;  C = g_D;   break;
    }
    const int Kd = 1024, Nd = 1024;
    __shared__ float As[2][8][128];
    __shared__ float Bs[2][8][128];
    int tid = threadIdx.x;
    int blockRow = blockIdx.y;
    int blockCol = blockIdx.x;
    (void)Mrows;

    int tr = (tid / 16) * 8;
    int tc = (tid % 16) * 8;

    int aRow = tid >> 1;            // 0..127
    int aCol = (tid & 1) * 4;       // 0 or 4
    int bRow = tid >> 5;            // 0..7
    int bCol = (tid & 31) * 4;      // 0..124

    const float* Aptr = A + (size_t)(blockRow * 128 + aRow) * Kd + aCol;
    const float* Bptr = Bm + (size_t)bRow * Nd + blockCol * 128 + bCol;

    float acc[8][8];
#pragma unroll
    for (int i = 0; i < 8; i++)
#pragma unroll
        for (int j = 0; j < 8; j++) acc[i][j] = 0.f;

    // preload tile 0
    {
        float4 av = *(const float4*)(Aptr);
        float4 bv = *(const float4*)(Bptr);
        As[0][aCol + 0][aRow] = av.x;
        As[0][aCol + 1][aRow] = av.y;
        As[0][aCol + 2][aRow] = av.z;
        As[0][aCol + 3][aRow] = av.w;
        *(float4*)&Bs[0][bRow][bCol] = bv;
    }
    __syncthreads();

    const int NT = Kd / 8;   // 128 tiles
    for (int t = 0; t < NT; ++t) {
        int cur = t & 1;
        float4 av2, bv2;
        if (t < NT - 1) {
            av2 = *(const float4*)(Aptr + (t + 1) * 8);
            bv2 = *(const float4*)(Bptr + (size_t)(t + 1) * 8 * Nd);
        }
#pragma unroll
        for (int k = 0; k < 8; ++k) {
            float4 a0 = *(const float4*)&As[cur][k][tr];
            float4 a1 = *(const float4*)&As[cur][k][tr + 4];
            float4 b0 = *(const float4*)&Bs[cur][k][tc];
            float4 b1 = *(const float4*)&Bs[cur][k][tc + 4];
            float av_[8] = {a0.x, a0.y, a0.z, a0.w, a1.x, a1.y, a1.z, a1.w};
            float bv_[8] = {b0.x, b0.y, b0.z, b0.w, b1.x, b1.y, b1.z, b1.w};
#pragma unroll
            for (int i = 0; i < 8; i++)
#pragma unroll
                for (int j = 0; j < 8; j++)
                    acc[i][j] += av_[i] * bv_[j];
        }
        if (t < NT - 1) {
            int nxt = cur ^ 1;
            As[nxt][aCol + 0][aRow] = av2.x;
            As[nxt][aCol + 1][aRow] = av2.y;
            As[nxt][aCol + 2][aRow] = av2.z;
            As[nxt][aCol + 3][aRow] = av2.w;
            *(float4*)&Bs[nxt][bRow][bCol] = bv2;
            __syncthreads();
        }
    }

    int row0 = blockRow * 128 + tr;
    int col0 = blockCol * 128 + tc;
#pragma unroll
    for (int i = 0; i < 8; i++) {
        float4 v0 = make_float4(acc[i][0], acc[i][1], acc[i][2], acc[i][3]);
        float4 v1 = make_float4(acc[i][4], acc[i][5], acc[i][6], acc[i][7]);
        *(float4*)&C[(size_t)(row0 + i) * Nd + col0]     = v0;
        *(float4*)&C[(size_t)(row0 + i) * Nd + col0 + 4] = v1;
    }
}

// ---------------- init: N_k = T - P_k;  a = A_k + E - N_k at own cells; s = sigmoid(a) ----------------
__global__ void init_k() {
    int idx = blockIdx.x * blockDim.x + threadIdx.x;
    if (idx >= KSTRIDE) return;
    float P0 = g_P[0*KSTRIDE + idx];
    float P1 = g_P[1*KSTRIDE + idx];
    float P2 = g_P[2*KSTRIDE + idx];
    float P3 = g_P[3*KSTRIDE + idx];
    float T = P0 + P1 + P2 + P3;
    g_N[0*KSTRIDE + idx] = T - P0;
    g_N[1*KSTRIDE + idx] = T - P1;
    g_N[2*KSTRIDE + idx] = T - P2;
    g_N[3*KSTRIDE + idx] = T - P3;
    int c = g_cls[idx];
    float a = 0.f, s = 0.5f;
    if (c != 0) {
        int k = c - 1;
        float Pk = (k == 0) ? P0 : (k == 1) ? P1 : (k == 2) ? P2 : P3;
        a = g_Aea[k*KSTRIDE + idx] + g_E[idx] - (T - Pk);
        s = 1.f / (1.f + expf(-a));
    }
    g_a[idx] = a;
    g_s[idx] = s;
}

// ---------------- X = N * s (broadcast over k) ----------------
__global__ void xmul_k() {
    int idx = blockIdx.x * blockDim.x + threadIdx.x;
    if (idx >= 4*KSTRIDE) return;
    g_X[idx] = g_N[idx] * g_s[idx & (KSTRIDE - 1)];
}

// ---------------- diffusion update: a += E + D_{k(cell)}; s = sigmoid(a) ----------------
__global__ void update_k() {
    int idx = blockIdx.x * blockDim.x + threadIdx.x;
    if (idx >= KSTRIDE) return;
    int c = g_cls[idx];
    if (c != 0) {
        float a = g_a[idx] + g_E[idx] + g_D[(c - 1)*KSTRIDE + idx];
        g_a[idx] = a;
        g_s[idx] = 1.f / (1.f + expf(-a));
    }
}

// ---------------- MLP head ----------------
__global__ void mlp1_k(const float* __restrict__ W1) {
    int gw = (blockIdx.x * blockDim.x + threadIdx.x) >> 5;
    int lane = threadIdx.x & 31;
    if (gw >= BATCH * 100) return;
    int b = gw / 100, j = gw % 100;
    const float* srow = g_s + (size_t)b * 1024;
    const float* wrow = W1 + (size_t)j * 1024;
    float acc = 0.f;
#pragma unroll 8
    for (int t = lane; t < 1024; t += 32) acc += srow[t] * wrow[t];
#pragma unroll
    for (int o = 16; o; o >>= 1) acc += __shfl_xor_sync(0xffffffffu, acc, o);
    if (lane == 0) g_x1[b * 100 + j] = (acc > 0.f) ? acc : 0.2f * acc;
}

__global__ void mlp2_k(const float* __restrict__ W2) {
    int gw = (blockIdx.x * blockDim.x + threadIdx.x) >> 5;
    int lane = threadIdx.x & 31;
    if (gw >= BATCH * 100) return;
    int b = gw / 100, j = gw % 100;
    const float* xrow = g_x1 + (size_t)b * 100;
    const float* wrow = W2 + (size_t)j * 100;
    float acc = 0.f;
    for (int t = lane; t < 100; t += 32) acc += xrow[t] * wrow[t];
#pragma unroll
    for (int o = 16; o; o >>= 1) acc += __shfl_xor_sync(0xffffffffu, acc, o);
    if (lane == 0) g_x2[b * 100 + j] = (acc > 0.f) ? acc : 0.2f * acc;
}

__global__ void mlp3_k(const float* __restrict__ W3, float* __restrict__ out) {
    int gw = (blockIdx.x * blockDim.x + threadIdx.x) >> 5;
    int lane = threadIdx.x & 31;
    if (gw >= BATCH) return;
    const float* xrow = g_x2 + (size_t)gw * 100;
    float acc = 0.f;
    for (int t = lane; t < 100; t += 32) acc += xrow[t] * W3[t];
#pragma unroll
    for (int o = 16; o; o >>= 1) acc += __shfl_xor_sync(0xffffffffu, acc, o);
    if (lane == 0) out[gw] = acc;
}

// ---------------- launch ----------------
extern "C" void kernel_launch(void* const* d_in, const int* in_sizes, int n_in,
                              void* d_out, int out_size) {
    (void)in_sizes; (void)n_in; (void)out_size;
    const int*   dots    = (const int*)d_in[0];
    const float* w_each  = (const float*)d_in[1];
    const float* w_not   = (const float*)d_in[2];
    const float* w_not2  = (const float*)d_in[3];
    const float* w_empty = (const float*)d_in[4];
    const float* W1      = (const float*)d_in[5];
    const float* W2      = (const float*)d_in[6];
    const float* W3      = (const float*)d_in[7];
    float* out = (float*)d_out;

    // 1) conv matrices
    build_M_k<<<(CELLS*CELLS + 255)/256, 256>>>(w_each, w_not, w_not2, w_empty);

    // 2) masks
    build_masks_k<<<(KSTRIDE + 255)/256, 256>>>(dots);

    // 3) phase-A GEMMs
    {
        dim3 gE(8, BATCH/128);
        sgemm_k<<<gE, 256>>>(0, BATCH);          // E
        dim3 g4(8, 4*BATCH/128);
        sgemm_k<<<g4, 256>>>(1, 4*BATCH);        // Aea
        sgemm_k<<<g4, 256>>>(2, 4*BATCH);        // P
    }

    // 4) init a, s, N
    init_k<<<(KSTRIDE + 255)/256, 256>>>();

    // 5) 4 diffusion depths
    for (int d = 0; d < 4; d++) {
        xmul_k<<<(4*KSTRIDE + 255)/256, 256>>>();
        dim3 g4(8, 4*BATCH/128);
        sgemm_k<<<g4, 256>>>(3, 4*BATCH);        // D = X @ M_not2
        update_k<<<(KSTRIDE + 255)/256, 256>>>();
    }

    // 6) MLP head
    {
        long nw1 = (long)BATCH * 100 * 32;
        mlp1_k<<<(unsigned)((nw1 + 255)/256), 256>>>(W1);
        mlp2_k<<<(unsigned)((nw1 + 255)/256), 256>>>(W2);
        long nw3 = (long)BATCH * 32;
        mlp3_k<<<(unsigned)((nw3 + 255)/256), 256>>>(W3, out);
    }
}

// round 8
// speedup vs baseline: 2.1228x; 2.1228x over previous
#include <cuda_runtime.h>
#include <cuda_bf16.h>
#include <math.h>
#include <stdint.h>

#define BATCH 4096
#define CELLS 1024
#define KSTRIDE (BATCH*CELLS)   // 4194304 elements per (k) slab

// ======================= helpers (baseline PTX only, no 'a'-features) =======================
__device__ __forceinline__ uint32_t smem_to_u32(const void* smem_ptr) {
    uint32_t addr;
    asm("{ .reg .u64 tmp; cvta.to.shared.u64 tmp, %1; cvt.u32.u64 %0, tmp; }"
        : "=r"(addr) : "l"(smem_ptr));
    return addr;
}
#define LDSM_X4(r, addr) \
    asm volatile("ldmatrix.sync.aligned.m8n8.x4.shared.b16 {%0,%1,%2,%3}, [%4];" \
        : "=r"((r)[0]), "=r"((r)[1]), "=r"((r)[2]), "=r"((r)[3]) : "r"(addr))
#define CP_ASYNC_16(dst, src) \
    asm volatile("cp.async.cg.shared.global [%0], [%1], 16;" :: "r"(dst), "l"(src) : "memory")
#define CP_ASYNC_COMMIT() asm volatile("cp.async.commit_group;" ::: "memory")
#define CP_ASYNC_WAIT_1() asm volatile("cp.async.wait_group 1;" ::: "memory")
#define CP_ASYNC_WAIT_0() asm volatile("cp.async.wait_group 0;" ::: "memory")

__device__ __forceinline__ void mma_16816_bf16(float* c, const uint32_t* a,
                                               uint32_t b0, uint32_t b1) {
    asm volatile(
        "mma.sync.aligned.m16n8k16.row.col.f32.bf16.bf16.f32 "
        "{%0,%1,%2,%3}, {%4,%5,%6,%7}, {%8,%9}, {%0,%1,%2,%3};"
        : "+f"(c[0]), "+f"(c[1]), "+f"(c[2]), "+f"(c[3])
        : "r"(a[0]), "r"(a[1]), "r"(a[2]), "r"(a[3]), "r"(b0), "r"(b1));
}

// ======================= device global scratch =======================
// conv matrices, transposed for MMA (B[n][k] = M[k][n]), split into bf16 hi/lo
__device__ __nv_bfloat16 g_Bhi_empty[CELLS*CELLS];
__device__ __nv_bfloat16 g_Blo_empty[CELLS*CELLS];
__device__ __nv_bfloat16 g_Bhi_each [CELLS*CELLS];
__device__ __nv_bfloat16 g_Blo_each [CELLS*CELLS];
__device__ __nv_bfloat16 g_Bhi_not  [CELLS*CELLS];
__device__ __nv_bfloat16 g_Blo_not  [CELLS*CELLS];
__device__ __nv_bfloat16 g_Bhi_not2 [CELLS*CELLS];
__device__ __nv_bfloat16 g_Blo_not2 [CELLS*CELLS];

__device__ __nv_bfloat16 g_emptyA[KSTRIDE];       // exact 0/1 masks in bf16
__device__ __nv_bfloat16 g_eachA [4*KSTRIDE];
__device__ __nv_bfloat16 g_Xhi   [4*KSTRIDE];     // split of X = N*s
__device__ __nv_bfloat16 g_Xlo   [4*KSTRIDE];

__device__ float g_E  [KSTRIDE];
__device__ float g_Aea[4*KSTRIDE];
__device__ float g_P  [4*KSTRIDE];
__device__ float g_N  [4*KSTRIDE];
__device__ float g_D  [4*KSTRIDE];
__device__ float g_a  [KSTRIDE];
__device__ float g_s  [KSTRIDE];
__device__ unsigned char g_cls[KSTRIDE];
__device__ float g_x1[BATCH*100];
__device__ float g_x2[BATCH*100];

// ======= build transposed conv matrices, split to bf16 hi/lo =======
__global__ void build_B_k(const float* __restrict__ w_each,
                          const float* __restrict__ w_not,
                          const float* __restrict__ w_not2,
                          const float* __restrict__ w_empty) {
    int idx = blockIdx.x * blockDim.x + threadIdx.x;
    if (idx >= CELLS*CELLS) return;
    int n = idx >> 10;      // output cell (row of B)
    int k = idx & 1023;     // input cell  (col of B)
    int ny = n >> 5, nx = n & 31;
    int kv = k >> 5, kh = k & 31;
    int dy = kv - ny + 16, dx = kh - nx + 16;
    float we = 0.f, wa = 0.f, wn = 0.f, w2 = 0.f;
    if ((unsigned)dy < 33u && (unsigned)dx < 33u) {
        int wi = dy * 33 + dx;
        we = w_empty[wi]; wa = w_each[wi]; wn = w_not[wi]; w2 = w_not2[wi];
    }
    __nv_bfloat16 h;
    h = __float2bfloat16(we); g_Bhi_empty[idx] = h; g_Blo_empty[idx] = __float2bfloat16(we - __bfloat162float(h));
    h = __float2bfloat16(wa); g_Bhi_each [idx] = h; g_Blo_each [idx] = __float2bfloat16(wa - __bfloat162float(h));
    h = __float2bfloat16(wn); g_Bhi_not  [idx] = h; g_Blo_not  [idx] = __float2bfloat16(wn - __bfloat162float(h));
    h = __float2bfloat16(w2); g_Bhi_not2 [idx] = h; g_Blo_not2 [idx] = __float2bfloat16(w2 - __bfloat162float(h));
}

// ======= masks (bf16, exact 0/1) =======
__global__ void build_masks_k(const int* __restrict__ dots) {
    int idx = blockIdx.x * blockDim.x + threadIdx.x;
    if (idx >= KSTRIDE) return;
    int b = idx >> 10;
    int i = idx & 1023;
    int c = dots[i * BATCH + b];   // dots[(v*32+h)*B + b]
    g_cls[idx] = (unsigned char)c;
    g_emptyA[idx] = __float2bfloat16((c == 0) ? 1.f : 0.f);
#pragma unroll
    for (int k = 0; k < 4; k++)
        g_eachA[k*KSTRIDE + idx] = __float2bfloat16((c == k + 1) ? 1.f : 0.f);
}

// ======= bf16 mma.sync GEMM: C[rows x 1024] = sum_seg Aseg @ Bseg^T =======
// CTA tile 128x128, Kt=32, double-buffered cp.async, 8 warps (2M x 4N),
// warp tile 64x32, mma.m16n8k16 bf16. K segments of 1024 implement hi/lo split.
// sel: 0=E(2seg), 1=Aea(2seg), 2=P(2seg), 3=D(3seg diffusion)
#define ROWB 80   // padded smem row stride in bytes (32 bf16 = 64B data + 16B pad)
__global__ __launch_bounds__(256)
void mma_gemm_k(int sel) {
    const __nv_bfloat16 *A0, *A1, *A2 = nullptr;
    const __nv_bfloat16 *B0, *B1, *B2 = nullptr;
    float* C;
    int nseg;
    switch (sel) {
        case 0:  A0 = A1 = g_emptyA; B0 = g_Bhi_empty; B1 = g_Blo_empty; C = g_E;   nseg = 2; break;
        case 1:  A0 = A1 = g_eachA;  B0 = g_Bhi_each;  B1 = g_Blo_each;  C = g_Aea; nseg = 2; break;
        case 2:  A0 = A1 = g_eachA;  B0 = g_Bhi_not;   B1 = g_Blo_not;   C = g_P;   nseg = 2; break;
        default: A0 = A1 = g_Xhi; A2 = g_Xlo;
                 B0 = g_Bhi_not2; B1 = g_Blo_not2; B2 = g_Bhi_not2;      C = g_D;   nseg = 3; break;
    }

    __shared__ __align__(16) unsigned char smA[2][128*ROWB];
    __shared__ __align__(16) unsigned char smB[2][128*ROWB];
    const uint32_t sA = smem_to_u32(smA);
    const uint32_t sB = smem_to_u32(smB);

    const int tid  = threadIdx.x;
    const int lane = tid & 31;
    const int wid  = tid >> 5;
    const int wm   = wid & 1;          // 2 warps along M
    const int wn   = wid >> 1;         // 4 warps along N
    const size_t mBase = (size_t)blockIdx.y * 128;
    const size_t nBase = (size_t)blockIdx.x * 128;

    const int NT = nseg * 32;          // 32 Kt-tiles per 1024-K segment

    // thread's two 16B chunks per matrix per tile
    const int ch0 = tid, ch1 = tid + 256;       // 512 chunks: row=ch>>2, c=ch&3
    const int r0c = ch0 >> 2, c0c = ch0 & 3;
    const int r1c = ch1 >> 2, c1c = ch1 & 3;

    float acc[4][4][4];
#pragma unroll
    for (int i = 0; i < 4; i++)
#pragma unroll
        for (int j = 0; j < 4; j++)
#pragma unroll
            for (int q = 0; q < 4; q++) acc[i][j][q] = 0.f;

    // ---- issue loads for tile t into buffer buf ----
    auto issue_tile = [&](int t, int buf) {
        int seg = t >> 5, kk = (t & 31) * 32;
        const __nv_bfloat16* As = (seg == 0) ? A0 : ((seg == 1) ? A1 : A2);
        const __nv_bfloat16* Bs = (seg == 0) ? B0 : ((seg == 1) ? B1 : B2);
        uint32_t da0 = sA + buf * (128*ROWB) + r0c * ROWB + c0c * 16;
        uint32_t da1 = sA + buf * (128*ROWB) + r1c * ROWB + c1c * 16;
        uint32_t db0 = sB + buf * (128*ROWB) + r0c * ROWB + c0c * 16;
        uint32_t db1 = sB + buf * (128*ROWB) + r1c * ROWB + c1c * 16;
        CP_ASYNC_16(da0, As + (mBase + r0c) * 1024 + kk + c0c * 8);
        CP_ASYNC_16(da1, As + (mBase + r1c) * 1024 + kk + c1c * 8);
        CP_ASYNC_16(db0, Bs + (nBase + r0c) * 1024 + kk + c0c * 8);
        CP_ASYNC_16(db1, Bs + (nBase + r1c) * 1024 + kk + c1c * 8);
        CP_ASYNC_COMMIT();
    };

    issue_tile(0, 0);

    for (int t = 0; t < NT; ++t) {
        int buf = t & 1;
        if (t + 1 < NT) { issue_tile(t + 1, buf ^ 1); CP_ASYNC_WAIT_1(); }
        else            { CP_ASYNC_WAIT_0(); }
        __syncthreads();

        uint32_t aB = sA + buf * (128*ROWB);
        uint32_t bB = sB + buf * (128*ROWB);
#pragma unroll
        for (int ks = 0; ks < 2; ks++) {
            uint32_t afr[4][4];
#pragma unroll
            for (int mi = 0; mi < 4; mi++) {
                uint32_t addr = aB + (uint32_t)(wm * 64 + mi * 16 + (lane & 15)) * ROWB
                              + (uint32_t)(ks * 32 + (lane >> 4) * 16);
                LDSM_X4(afr[mi], addr);
            }
            uint32_t bfr[2][4];
#pragma unroll
            for (int nb = 0; nb < 2; nb++) {
                uint32_t addr = bB + (uint32_t)(wn * 32 + nb * 16 + (lane & 15)) * ROWB
                              + (uint32_t)(ks * 32 + (lane >> 4) * 16);
                LDSM_X4(bfr[nb], addr);
            }
#pragma unroll
            for (int mi = 0; mi < 4; mi++)
#pragma unroll
                for (int ni = 0; ni < 4; ni++) {
                    int nb = ni >> 1, j = ni & 1;
                    mma_16816_bf16(acc[mi][ni], afr[mi], bfr[nb][j], bfr[nb][j + 2]);
                }
        }
        __syncthreads();
    }

    // ---- epilogue: write fp32 C ----
    const int g  = lane >> 2;
    const int t2 = (lane & 3) * 2;
#pragma unroll
    for (int mi = 0; mi < 4; mi++) {
#pragma unroll
        for (int ni = 0; ni < 4; ni++) {
            size_t r = mBase + (size_t)(wm * 64 + mi * 16 + g);
            size_t c = nBase + (size_t)(wn * 32 + ni * 8 + t2);
            *(float2*)&C[r * 1024 + c]       = make_float2(acc[mi][ni][0], acc[mi][ni][1]);
            *(float2*)&C[(r + 8) * 1024 + c] = make_float2(acc[mi][ni][2], acc[mi][ni][3]);
        }
    }
}

// ======= init: N_k = T - P_k;  a = A_k + E - N_k at own cells; s = sigmoid(a) =======
__global__ void init_k() {
    int idx = blockIdx.x * blockDim.x + threadIdx.x;
    if (idx >= KSTRIDE) return;
    float P0 = g_P[0*KSTRIDE + idx];
    float P1 = g_P[1*KSTRIDE + idx];
    float P2 = g_P[2*KSTRIDE + idx];
    float P3 = g_P[3*KSTRIDE + idx];
    float T = P0 + P1 + P2 + P3;
    g_N[0*KSTRIDE + idx] = T - P0;
    g_N[1*KSTRIDE + idx] = T - P1;
    g_N[2*KSTRIDE + idx] = T - P2;
    g_N[3*KSTRIDE + idx] = T - P3;
    int c = g_cls[idx];
    float a = 0.f, s = 0.5f;
    if (c != 0) {
        int k = c - 1;
        float Pk = (k == 0) ? P0 : (k == 1) ? P1 : (k == 2) ? P2 : P3;
        a = g_Aea[k*KSTRIDE + idx] + g_E[idx] - (T - Pk);
        s = 1.f / (1.f + expf(-a));
    }
    g_a[idx] = a;
    g_s[idx] = s;
}

// ======= X = N * s, split to bf16 hi/lo =======
__global__ void xmul_k() {
    int idx = blockIdx.x * blockDim.x + threadIdx.x;
    if (idx >= 4*KSTRIDE) return;
    float x = g_N[idx] * g_s[idx & (KSTRIDE - 1)];
    __nv_bfloat16 h = __float2bfloat16(x);
    g_Xhi[idx] = h;
    g_Xlo[idx] = __float2bfloat16(x - __bfloat162float(h));
}

// ======= diffusion update: a += E + D_{k(cell)}; s = sigmoid(a) =======
__global__ void update_k() {
    int idx = blockIdx.x * blockDim.x + threadIdx.x;
    if (idx >= KSTRIDE) return;
    int c = g_cls[idx];
    if (c != 0) {
        float a = g_a[idx] + g_E[idx] + g_D[(c - 1)*KSTRIDE + idx];
        g_a[idx] = a;
        g_s[idx] = 1.f / (1.f + expf(-a));
    }
}

// ======= MLP head =======
// x1 = leaky(s @ W1^T): tiled, block = 64 rows x 100 cols
__global__ __launch_bounds__(256)
void mlp1_k(const float* __restrict__ W1) {
    __shared__ float sS[64][65];
    __shared__ float sW[100][65];
    int tid = threadIdx.x;
    int rowBase = blockIdx.x * 64;
    float acc[25];
#pragma unroll
    for (int i = 0; i < 25; i++) acc[i] = 0.f;
    int r = tid >> 2, cs = (tid & 3) * 25;
    for (int k0 = 0; k0 < 1024; k0 += 64) {
#pragma unroll
        for (int i = 0; i < 16; i++) {
            int e = tid + i * 256; int rr = e >> 6, c = e & 63;
            sS[rr][c] = g_s[(size_t)(rowBase + rr) * 1024 + k0 + c];
        }
#pragma unroll
        for (int i = 0; i < 25; i++) {
            int e = tid + i * 256; int j = e >> 6, c = e & 63;
            sW[j][c] = W1[(size_t)j * 1024 + k0 + c];
        }
        __syncthreads();
#pragma unroll 8
        for (int k = 0; k < 64; k++) {
            float sv = sS[r][k];
#pragma unroll
            for (int j = 0; j < 25; j++) acc[j] += sv * sW[cs + j][k];
        }
        __syncthreads();
    }
#pragma unroll
    for (int j = 0; j < 25; j++) {
        float v = acc[j];
        g_x1[(size_t)(rowBase + r) * 100 + cs + j] = (v > 0.f) ? v : 0.2f * v;
    }
}

__global__ void mlp2_k(const float* __restrict__ W2) {
    int gw = (blockIdx.x * blockDim.x + threadIdx.x) >> 5;
    int lane = threadIdx.x & 31;
    if (gw >= BATCH * 100) return;
    int b = gw / 100, j = gw % 100;
    const float* xrow = g_x1 + (size_t)b * 100;
    const float* wrow = W2 + (size_t)j * 100;
    float acc = 0.f;
    for (int t = lane; t < 100; t += 32) acc += xrow[t] * wrow[t];
#pragma unroll
    for (int o = 16; o; o >>= 1) acc += __shfl_xor_sync(0xffffffffu, acc, o);
    if (lane == 0) g_x2[b * 100 + j] = (acc > 0.f) ? acc : 0.2f * acc;
}

__global__ void mlp3_k(const float* __restrict__ W3, float* __restrict__ out) {
    int gw = (blockIdx.x * blockDim.x + threadIdx.x) >> 5;
    int lane = threadIdx.x & 31;
    if (gw >= BATCH) return;
    const float* xrow = g_x2 + (size_t)gw * 100;
    float acc = 0.f;
    for (int t = lane; t < 100; t += 32) acc += xrow[t] * W3[t];
#pragma unroll
    for (int o = 16; o; o >>= 1) acc += __shfl_xor_sync(0xffffffffu, acc, o);
    if (lane == 0) out[gw] = acc;
}

// ======= launch =======
extern "C" void kernel_launch(void* const* d_in, const int* in_sizes, int n_in,
                              void* d_out, int out_size) {
    (void)in_sizes; (void)n_in; (void)out_size;
    const int*   dots    = (const int*)d_in[0];
    const float* w_each  = (const float*)d_in[1];
    const float* w_not   = (const float*)d_in[2];
    const float* w_not2  = (const float*)d_in[3];
    const float* w_empty = (const float*)d_in[4];
    const float* W1      = (const float*)d_in[5];
    const float* W2      = (const float*)d_in[6];
    const float* W3      = (const float*)d_in[7];
    float* out = (float*)d_out;

    build_B_k<<<(CELLS*CELLS + 255)/256, 256>>>(w_each, w_not, w_not2, w_empty);
    build_masks_k<<<(KSTRIDE + 255)/256, 256>>>(dots);

    // phase-A GEMMs on tensor cores (split-bf16, K=2048)
    mma_gemm_k<<<dim3(8, 32),  256>>>(0);   // E   (4096 rows)
    mma_gemm_k<<<dim3(8, 128), 256>>>(1);   // Aea (16384 rows)
    mma_gemm_k<<<dim3(8, 128), 256>>>(2);   // P   (16384 rows)

    init_k<<<(KSTRIDE + 255)/256, 256>>>();

    for (int d = 0; d < 4; d++) {
        xmul_k<<<(4*KSTRIDE + 255)/256, 256>>>();
        mma_gemm_k<<<dim3(8, 128), 256>>>(3);   // D (3-term split, K=3072)
        update_k<<<(KSTRIDE + 255)/256, 256>>>();
    }

    mlp1_k<<<BATCH/64, 256>>>(W1);
    {
        long nw = (long)BATCH * 100 * 32;
        mlp2_k<<<(unsigned)((nw + 255)/256), 256>>>(W2);
        long nw3 = (long)BATCH * 32;
        mlp3_k<<<(unsigned)((nw3 + 255)/256), 256>>>(W3, out);
    }
}

// round 9
// speedup vs baseline: 2.2895x; 1.0786x over previous
#include <cuda_runtime.h>
#include <cuda_bf16.h>
#include <math.h>
#include <stdint.h>

#define BATCH 4096
#define CELLS 1024
#define KSTRIDE (BATCH*CELLS)   // 4194304 elements per (k) slab

// ======================= helpers (baseline PTX only, no 'a'-features) =======================
__device__ __forceinline__ uint32_t smem_to_u32(const void* smem_ptr) {
    uint32_t addr;
    asm("{ .reg .u64 tmp; cvta.to.shared.u64 tmp, %1; cvt.u32.u64 %0, tmp; }"
        : "=r"(addr) : "l"(smem_ptr));
    return addr;
}
#define LDSM_X4(r, addr) \
    asm volatile("ldmatrix.sync.aligned.m8n8.x4.shared.b16 {%0,%1,%2,%3}, [%4];" \
        : "=r"((r)[0]), "=r"((r)[1]), "=r"((r)[2]), "=r"((r)[3]) : "r"(addr))
#define CP_ASYNC_16(dst, src) \
    asm volatile("cp.async.cg.shared.global [%0], [%1], 16;" :: "r"(dst), "l"(src) : "memory")
#define CP_ASYNC_COMMIT() asm volatile("cp.async.commit_group;" ::: "memory")
#define CP_ASYNC_WAIT_1() asm volatile("cp.async.wait_group 1;" ::: "memory")
#define CP_ASYNC_WAIT_0() asm volatile("cp.async.wait_group 0;" ::: "memory")

__device__ __forceinline__ void mma_16816_bf16(float* c, const uint32_t* a,
                                               uint32_t b0, uint32_t b1) {
    asm volatile(
        "mma.sync.aligned.m16n8k16.row.col.f32.bf16.bf16.f32 "
        "{%0,%1,%2,%3}, {%4,%5,%6,%7}, {%8,%9}, {%0,%1,%2,%3};"
        : "+f"(c[0]), "+f"(c[1]), "+f"(c[2]), "+f"(c[3])
        : "r"(a[0]), "r"(a[1]), "r"(a[2]), "r"(a[3]), "r"(b0), "r"(b1));
}

// ======================= device global scratch =======================
// conv matrices, transposed for MMA (B[n][k] = M[k][n]), split into bf16 hi/lo
__device__ __nv_bfloat16 g_Bhi_empty[CELLS*CELLS];
__device__ __nv_bfloat16 g_Blo_empty[CELLS*CELLS];
__device__ __nv_bfloat16 g_Bhi_each [CELLS*CELLS];
__device__ __nv_bfloat16 g_Blo_each [CELLS*CELLS];
__device__ __nv_bfloat16 g_Bhi_not  [CELLS*CELLS];
__device__ __nv_bfloat16 g_Blo_not  [CELLS*CELLS];
__device__ __nv_bfloat16 g_Bhi_not2 [CELLS*CELLS];
__device__ __nv_bfloat16 g_Blo_not2 [CELLS*CELLS];

__device__ __nv_bfloat16 g_emptyA[KSTRIDE];       // exact 0/1 masks in bf16
__device__ __nv_bfloat16 g_eachA [4*KSTRIDE];
__device__ __nv_bfloat16 g_Xhi   [4*KSTRIDE];     // split of X = N*s
__device__ __nv_bfloat16 g_Xlo   [4*KSTRIDE];

__device__ float g_E  [KSTRIDE];
__device__ float g_Aea[4*KSTRIDE];
__device__ float g_P  [4*KSTRIDE];
__device__ float g_N  [4*KSTRIDE];
__device__ float g_D  [4*KSTRIDE];
__device__ float g_a  [KSTRIDE];
__device__ float g_s  [KSTRIDE];
__device__ unsigned char g_cls[KSTRIDE];
__device__ float g_x1[BATCH*100];
__device__ float g_x2[BATCH*100];

// ======= build transposed conv matrices, split to bf16 hi/lo =======
__global__ void build_B_k(const float* __restrict__ w_each,
                          const float* __restrict__ w_not,
                          const float* __restrict__ w_not2,
                          const float* __restrict__ w_empty) {
    int idx = blockIdx.x * blockDim.x + threadIdx.x;
    if (idx >= CELLS*CELLS) return;
    int n = idx >> 10;      // output cell (row of B)
    int k = idx & 1023;     // input cell  (col of B)
    int ny = n >> 5, nx = n & 31;
    int kv = k >> 5, kh = k & 31;
    int dy = kv - ny + 16, dx = kh - nx + 16;
    float we = 0.f, wa = 0.f, wn = 0.f, w2 = 0.f;
    if ((unsigned)dy < 33u && (unsigned)dx < 33u) {
        int wi = dy * 33 + dx;
        we = w_empty[wi]; wa = w_each[wi]; wn = w_not[wi]; w2 = w_not2[wi];
    }
    __nv_bfloat16 h;
    h = __float2bfloat16(we); g_Bhi_empty[idx] = h; g_Blo_empty[idx] = __float2bfloat16(we - __bfloat162float(h));
    h = __float2bfloat16(wa); g_Bhi_each [idx] = h; g_Blo_each [idx] = __float2bfloat16(wa - __bfloat162float(h));
    h = __float2bfloat16(wn); g_Bhi_not  [idx] = h; g_Blo_not  [idx] = __float2bfloat16(wn - __bfloat162float(h));
    h = __float2bfloat16(w2); g_Bhi_not2 [idx] = h; g_Blo_not2 [idx] = __float2bfloat16(w2 - __bfloat162float(h));
}

// ======= masks (bf16, exact 0/1) =======
__global__ void build_masks_k(const int* __restrict__ dots) {
    int idx = blockIdx.x * blockDim.x + threadIdx.x;
    if (idx >= KSTRIDE) return;
    int b = idx >> 10;
    int i = idx & 1023;
    int c = dots[i * BATCH + b];   // dots[(v*32+h)*B + b]
    g_cls[idx] = (unsigned char)c;
    g_emptyA[idx] = __float2bfloat16((c == 0) ? 1.f : 0.f);
#pragma unroll
    for (int k = 0; k < 4; k++)
        g_eachA[k*KSTRIDE + idx] = __float2bfloat16((c == k + 1) ? 1.f : 0.f);
}

// ======= bf16 mma.sync GEMM: C[rows x 1024] = sum_seg Aseg @ Bseg^T =======
// CTA tile 128x128, Kt=32, 3-stage cp.async multistage (single sync/tile),
// 8 warps (2M x 4N), warp tile 64x32, mma.m16n8k16 bf16.
// sel: 0=E(2seg), 1=Aea+P combined (blockIdx.x selects half), 3=D(3seg)
#define ROWB 80                  // padded smem row stride in bytes
#define STAGEB (2*128*ROWB)      // A+B per stage = 20480
extern __shared__ unsigned char dyn_smem[];

__global__ __launch_bounds__(256)
void mma_gemm_k(int sel) {
    const __nv_bfloat16 *A0, *A1, *A2 = nullptr;
    const __nv_bfloat16 *B0, *B1, *B2 = nullptr;
    float* C;
    int nseg;
    int bx = blockIdx.x;
    size_t nBase;
    if (sel == 0) {
        A0 = A1 = g_emptyA; B0 = g_Bhi_empty; B1 = g_Blo_empty; C = g_E; nseg = 2;
        nBase = (size_t)bx * 128;
    } else if (sel == 1) {
        A0 = A1 = g_eachA; nseg = 2;
        if (bx < 8) { B0 = g_Bhi_each; B1 = g_Blo_each; C = g_Aea; nBase = (size_t)bx * 128; }
        else        { B0 = g_Bhi_not;  B1 = g_Blo_not;  C = g_P;   nBase = (size_t)(bx - 8) * 128; }
    } else {
        A0 = A1 = g_Xhi; A2 = g_Xlo;
        B0 = g_Bhi_not2; B1 = g_Blo_not2; B2 = g_Bhi_not2; C = g_D; nseg = 3;
        nBase = (size_t)bx * 128;
    }

    const uint32_t sBase = smem_to_u32(dyn_smem);

    const int tid  = threadIdx.x;
    const int lane = tid & 31;
    const int wid  = tid >> 5;
    const int wm   = wid & 1;          // 2 warps along M
    const int wn   = wid >> 1;         // 4 warps along N
    const size_t mBase = (size_t)blockIdx.y * 128;

    const int NT = nseg * 32;          // 32 Kt-tiles per 1024-K segment

    // thread's two 16B chunks per matrix per tile (512 chunks/matrix)
    const int r0c = tid >> 2,         c0c = tid & 3;
    const int r1c = (tid + 256) >> 2, c1c = tid & 3;   // +256 keeps c the same (256%4==0)

    float acc[4][4][4];
#pragma unroll
    for (int i = 0; i < 4; i++)
#pragma unroll
        for (int j = 0; j < 4; j++)
#pragma unroll
            for (int q = 0; q < 4; q++) acc[i][j][q] = 0.f;

    auto issue_tile = [&](int t, int stage) {
        int seg = t >> 5, kk = (t & 31) * 32;
        const __nv_bfloat16* As = (seg == 0) ? A0 : ((seg == 1) ? A1 : A2);
        const __nv_bfloat16* Bs = (seg == 0) ? B0 : ((seg == 1) ? B1 : B2);
        uint32_t base = sBase + (uint32_t)stage * STAGEB;
        CP_ASYNC_16(base + r0c * ROWB + c0c * 16,
                    As + (mBase + r0c) * 1024 + kk + c0c * 8);
        CP_ASYNC_16(base + r1c * ROWB + c1c * 16,
                    As + (mBase + r1c) * 1024 + kk + c1c * 8);
        CP_ASYNC_16(base + 128*ROWB + r0c * ROWB + c0c * 16,
                    Bs + (nBase + r0c) * 1024 + kk + c0c * 8);
        CP_ASYNC_16(base + 128*ROWB + r1c * ROWB + c1c * 16,
                    Bs + (nBase + r1c) * 1024 + kk + c1c * 8);
        CP_ASYNC_COMMIT();
    };

    issue_tile(0, 0);
    issue_tile(1, 1);

    int stage = 0;
    for (int t = 0; t < NT; ++t) {
        if (t < NT - 1) CP_ASYNC_WAIT_1();
        else            CP_ASYNC_WAIT_0();
        __syncthreads();

        uint32_t aB = sBase + (uint32_t)stage * STAGEB;
        uint32_t bB = aB + 128*ROWB;
#pragma unroll
        for (int ks = 0; ks < 2; ks++) {
            uint32_t afr[4][4];
#pragma unroll
            for (int mi = 0; mi < 4; mi++) {
                uint32_t addr = aB + (uint32_t)(wm * 64 + mi * 16 + (lane & 15)) * ROWB
                              + (uint32_t)(ks * 32 + (lane >> 4) * 16);
                LDSM_X4(afr[mi], addr);
            }
            uint32_t bfr[2][4];
#pragma unroll
            for (int nb = 0; nb < 2; nb++) {
                uint32_t addr = bB + (uint32_t)(wn * 32 + nb * 16 + (lane & 15)) * ROWB
                              + (uint32_t)(ks * 32 + (lane >> 4) * 16);
                LDSM_X4(bfr[nb], addr);
            }
#pragma unroll
            for (int mi = 0; mi < 4; mi++)
#pragma unroll
                for (int ni = 0; ni < 4; ni++) {
                    int nb = ni >> 1, j = ni & 1;
                    mma_16816_bf16(acc[mi][ni], afr[mi], bfr[nb][j], bfr[nb][j + 2]);
                }
        }
        if (t + 2 < NT) {
            int s2 = stage + 2; if (s2 >= 3) s2 -= 3;
            issue_tile(t + 2, s2);
        }
        if (++stage == 3) stage = 0;
    }

    // ---- epilogue: write fp32 C ----
    const int g  = lane >> 2;
    const int t2 = (lane & 3) * 2;
#pragma unroll
    for (int mi = 0; mi < 4; mi++) {
#pragma unroll
        for (int ni = 0; ni < 4; ni++) {
            size_t r = mBase + (size_t)(wm * 64 + mi * 16 + g);
            size_t c = nBase + (size_t)(wn * 32 + ni * 8 + t2);
            *(float2*)&C[r * 1024 + c]       = make_float2(acc[mi][ni][0], acc[mi][ni][1]);
            *(float2*)&C[(r + 8) * 1024 + c] = make_float2(acc[mi][ni][2], acc[mi][ni][3]);
        }
    }
}

// ======= init (fused): N_k = T - P_k; a,s; X_k = N_k * s split to bf16 =======
__global__ void init_k() {
    int idx = blockIdx.x * blockDim.x + threadIdx.x;
    if (idx >= KSTRIDE) return;
    float P0 = g_P[0*KSTRIDE + idx];
    float P1 = g_P[1*KSTRIDE + idx];
    float P2 = g_P[2*KSTRIDE + idx];
    float P3 = g_P[3*KSTRIDE + idx];
    float T = P0 + P1 + P2 + P3;
    float N0 = T - P0, N1 = T - P1, N2 = T - P2, N3 = T - P3;
    g_N[0*KSTRIDE + idx] = N0;
    g_N[1*KSTRIDE + idx] = N1;
    g_N[2*KSTRIDE + idx] = N2;
    g_N[3*KSTRIDE + idx] = N3;
    int c = g_cls[idx];
    float a = 0.f, s = 0.5f;
    if (c != 0) {
        int k = c - 1;
        float Nk = (k == 0) ? N0 : (k == 1) ? N1 : (k == 2) ? N2 : N3;
        a = g_Aea[k*KSTRIDE + idx] + g_E[idx] - Nk;
        s = 1.f / (1.f + expf(-a));
    }
    g_a[idx] = a;
    g_s[idx] = s;
    float Nv[4] = {N0, N1, N2, N3};
#pragma unroll
    for (int k = 0; k < 4; k++) {
        float x = Nv[k] * s;
        __nv_bfloat16 h = __float2bfloat16(x);
        g_Xhi[k*KSTRIDE + idx] = h;
        g_Xlo[k*KSTRIDE + idx] = __float2bfloat16(x - __bfloat162float(h));
    }
}

// ======= update (fused): a += E + D_cls; s; optionally X = N*s for next depth =======
__global__ void update_k(int write_x) {
    int idx = blockIdx.x * blockDim.x + threadIdx.x;
    if (idx >= KSTRIDE) return;
    int c = g_cls[idx];
    float s = 0.5f;
    if (c != 0) {
        float a = g_a[idx] + g_E[idx] + g_D[(c - 1)*KSTRIDE + idx];
        s = 1.f / (1.f + expf(-a));
        if (write_x) g_a[idx] = a;
        else         g_s[idx] = s;     // final depth: publish s for the MLP
    }
    if (write_x) {
#pragma unroll
        for (int k = 0; k < 4; k++) {
            float x = g_N[k*KSTRIDE + idx] * s;
            __nv_bfloat16 h = __float2bfloat16(x);
            g_Xhi[k*KSTRIDE + idx] = h;
            g_Xlo[k*KSTRIDE + idx] = __float2bfloat16(x - __bfloat162float(h));
        }
    }
}

// ======= MLP head =======
__global__ __launch_bounds__(256)
void mlp1_k(const float* __restrict__ W1) {
    __shared__ float sS[64][65];
    __shared__ float sW[100][65];
    int tid = threadIdx.x;
    int rowBase = blockIdx.x * 64;
    float acc[25];
#pragma unroll
    for (int i = 0; i < 25; i++) acc[i] = 0.f;
    int r = tid >> 2, cs = (tid & 3) * 25;
    for (int k0 = 0; k0 < 1024; k0 += 64) {
#pragma unroll
        for (int i = 0; i < 16; i++) {
            int e = tid + i * 256; int rr = e >> 6, c = e & 63;
            sS[rr][c] = g_s[(size_t)(rowBase + rr) * 1024 + k0 + c];
        }
#pragma unroll
        for (int i = 0; i < 25; i++) {
            int e = tid + i * 256; int j = e >> 6, c = e & 63;
            sW[j][c] = W1[(size_t)j * 1024 + k0 + c];
        }
        __syncthreads();
#pragma unroll 8
        for (int k = 0; k < 64; k++) {
            float sv = sS[r][k];
#pragma unroll
            for (int j = 0; j < 25; j++) acc[j] += sv * sW[cs + j][k];
        }
        __syncthreads();
    }
#pragma unroll
    for (int j = 0; j < 25; j++) {
        float v = acc[j];
        g_x1[(size_t)(rowBase + r) * 100 + cs + j] = (v > 0.f) ? v : 0.2f * v;
    }
}

__global__ void mlp2_k(const float* __restrict__ W2) {
    int gw = (blockIdx.x * blockDim.x + threadIdx.x) >> 5;
    int lane = threadIdx.x & 31;
    if (gw >= BATCH * 100) return;
    int b = gw / 100, j = gw % 100;
    const float* xrow = g_x1 + (size_t)b * 100;
    const float* wrow = W2 + (size_t)j * 100;
    float acc = 0.f;
    for (int t = lane; t < 100; t += 32) acc += xrow[t] * wrow[t];
#pragma unroll
    for (int o = 16; o; o >>= 1) acc += __shfl_xor_sync(0xffffffffu, acc, o);
    if (lane == 0) g_x2[b * 100 + j] = (acc > 0.f) ? acc : 0.2f * acc;
}

__global__ void mlp3_k(const float* __restrict__ W3, float* __restrict__ out) {
    int gw = (blockIdx.x * blockDim.x + threadIdx.x) >> 5;
    int lane = threadIdx.x & 31;
    if (gw >= BATCH) return;
    const float* xrow = g_x2 + (size_t)gw * 100;
    float acc = 0.f;
    for (int t = lane; t < 100; t += 32) acc += xrow[t] * W3[t];
#pragma unroll
    for (int o = 16; o; o >>= 1) acc += __shfl_xor_sync(0xffffffffu, acc, o);
    if (lane == 0) out[gw] = acc;
}

// ======= launch =======
extern "C" void kernel_launch(void* const* d_in, const int* in_sizes, int n_in,
                              void* d_out, int out_size) {
    (void)in_sizes; (void)n_in; (void)out_size;
    const int*   dots    = (const int*)d_in[0];
    const float* w_each  = (const float*)d_in[1];
    const float* w_not   = (const float*)d_in[2];
    const float* w_not2  = (const float*)d_in[3];
    const float* w_empty = (const float*)d_in[4];
    const float* W1      = (const float*)d_in[5];
    const float* W2      = (const float*)d_in[6];
    const float* W3      = (const float*)d_in[7];
    float* out = (float*)d_out;

    const int SMEM = 3 * STAGEB;   // 61440
    cudaFuncSetAttribute(mma_gemm_k, cudaFuncAttributeMaxDynamicSharedMemorySize, SMEM);

    build_B_k<<<(CELLS*CELLS + 255)/256, 256>>>(w_each, w_not, w_not2, w_empty);
    build_masks_k<<<(KSTRIDE + 255)/256, 256>>>(dots);

    mma_gemm_k<<<dim3(8, 32),   256, SMEM>>>(0);   // E
    mma_gemm_k<<<dim3(16, 128), 256, SMEM>>>(1);   // Aea + P combined

    init_k<<<(KSTRIDE + 255)/256, 256>>>();

    for (int d = 0; d < 4; d++) {
        mma_gemm_k<<<dim3(8, 128), 256, SMEM>>>(3);   // D (3-term split)
        update_k<<<(KSTRIDE + 255)/256, 256>>>(d < 3 ? 1 : 0);
    }

    mlp1_k<<<BATCH/64, 256>>>(W1);
    {
        long nw = (long)BATCH * 100 * 32;
        mlp2_k<<<(unsigned)((nw + 255)/256), 256>>>(W2);
        long nw3 = (long)BATCH * 32;
        mlp3_k<<<(unsigned)((nw3 + 255)/256), 256>>>(W3, out);
    }
}

// round 13
// speedup vs baseline: 2.3075x; 1.0078x over previous
#include <cuda_runtime.h>
#include <cuda_bf16.h>
#include <math.h>
#include <stdint.h>

#define BATCH 4096
#define CELLS 1024
#define KSTRIDE (BATCH*CELLS)   // 4194304 elements per (k) slab

// ======================= helpers (baseline PTX only) =======================
__device__ __forceinline__ uint32_t smem_to_u32(const void* smem_ptr) {
    uint32_t addr;
    asm("{ .reg .u64 tmp; cvta.to.shared.u64 tmp, %1; cvt.u32.u64 %0, tmp; }"
        : "=r"(addr) : "l"(smem_ptr));
    return addr;
}
#define LDSM_X4(r, addr) \
    asm volatile("ldmatrix.sync.aligned.m8n8.x4.shared.b16 {%0,%1,%2,%3}, [%4];" \
        : "=r"((r)[0]), "=r"((r)[1]), "=r"((r)[2]), "=r"((r)[3]) : "r"(addr))
#define CP_ASYNC_16(dst, src) \
    asm volatile("cp.async.cg.shared.global [%0], [%1], 16;" :: "r"(dst), "l"(src) : "memory")
#define CP_ASYNC_COMMIT() asm volatile("cp.async.commit_group;" ::: "memory")
#define CP_ASYNC_WAIT_2() asm volatile("cp.async.wait_group 2;" ::: "memory")
#define CP_ASYNC_WAIT_1() asm volatile("cp.async.wait_group 1;" ::: "memory")
#define CP_ASYNC_WAIT_0() asm volatile("cp.async.wait_group 0;" ::: "memory")

__device__ __forceinline__ void mma_16816_bf16(float* c, const uint32_t* a,
                                               uint32_t b0, uint32_t b1) {
    asm volatile(
        "mma.sync.aligned.m16n8k16.row.col.f32.bf16.bf16.f32 "
        "{%0,%1,%2,%3}, {%4,%5,%6,%7}, {%8,%9}, {%0,%1,%2,%3};"
        : "+f"(c[0]), "+f"(c[1]), "+f"(c[2]), "+f"(c[3])
        : "r"(a[0]), "r"(a[1]), "r"(a[2]), "r"(a[3]), "r"(b0), "r"(b1));
}

// ======================= device global scratch =======================
__device__ __nv_bfloat16 g_Bhi_empty[CELLS*CELLS];
__device__ __nv_bfloat16 g_Blo_empty[CELLS*CELLS];
__device__ __nv_bfloat16 g_Bhi_each [CELLS*CELLS];
__device__ __nv_bfloat16 g_Blo_each [CELLS*CELLS];
__device__ __nv_bfloat16 g_Bhi_not  [CELLS*CELLS];
__device__ __nv_bfloat16 g_Blo_not  [CELLS*CELLS];
__device__ __nv_bfloat16 g_Bhi_not2 [CELLS*CELLS];
__device__ __nv_bfloat16 g_Blo_not2 [CELLS*CELLS];

__device__ __nv_bfloat16 g_emptyA[KSTRIDE];       // exact 0/1 masks in bf16
__device__ __nv_bfloat16 g_eachA [4*KSTRIDE];
__device__ __nv_bfloat16 g_Xhi   [4*KSTRIDE];     // split of X = N*s
__device__ __nv_bfloat16 g_Xlo   [4*KSTRIDE];

__device__ float g_E   [KSTRIDE];
__device__ float g_P   [4*KSTRIDE];
__device__ float g_N   [4*KSTRIDE];
__device__ float g_Asel[KSTRIDE];    // Aea masked to own class, single slab
__device__ float g_Dsel[KSTRIDE];    // D masked to own class, single slab
__device__ float g_a   [KSTRIDE];
__device__ float g_s   [KSTRIDE];
__device__ unsigned char g_cls[KSTRIDE];
__device__ float g_x1[BATCH*100];
__device__ float g_x2[BATCH*100];

// ======= build transposed conv matrices, split to bf16 hi/lo =======
__global__ void build_B_k(const float* __restrict__ w_each,
                          const float* __restrict__ w_not,
                          const float* __restrict__ w_not2,
                          const float* __restrict__ w_empty) {
    int idx = blockIdx.x * blockDim.x + threadIdx.x;
    if (idx >= CELLS*CELLS) return;
    int n = idx >> 10;      // output cell (row of B)
    int k = idx & 1023;     // input cell  (col of B)
    int ny = n >> 5, nx = n & 31;
    int kv = k >> 5, kh = k & 31;
    int dy = kv - ny + 16, dx = kh - nx + 16;
    float we = 0.f, wa = 0.f, wn = 0.f, w2 = 0.f;
    if ((unsigned)dy < 33u && (unsigned)dx < 33u) {
        int wi = dy * 33 + dx;
        we = w_empty[wi]; wa = w_each[wi]; wn = w_not[wi]; w2 = w_not2[wi];
    }
    __nv_bfloat16 h;
    h = __float2bfloat16(we); g_Bhi_empty[idx] = h; g_Blo_empty[idx] = __float2bfloat16(we - __bfloat162float(h));
    h = __float2bfloat16(wa); g_Bhi_each [idx] = h; g_Blo_each [idx] = __float2bfloat16(wa - __bfloat162float(h));
    h = __float2bfloat16(wn); g_Bhi_not  [idx] = h; g_Blo_not  [idx] = __float2bfloat16(wn - __bfloat162float(h));
    h = __float2bfloat16(w2); g_Bhi_not2 [idx] = h; g_Blo_not2 [idx] = __float2bfloat16(w2 - __bfloat162float(h));
}

// ======= masks (bf16, exact 0/1) =======
__global__ void build_masks_k(const int* __restrict__ dots) {
    int idx = blockIdx.x * blockDim.x + threadIdx.x;
    if (idx >= KSTRIDE) return;
    int b = idx >> 10;
    int i = idx & 1023;
    int c = dots[i * BATCH + b];   // dots[(v*32+h)*B + b]
    g_cls[idx] = (unsigned char)c;
    g_emptyA[idx] = __float2bfloat16((c == 0) ? 1.f : 0.f);
#pragma unroll
    for (int k = 0; k < 4; k++)
        g_eachA[k*KSTRIDE + idx] = __float2bfloat16((c == k + 1) ? 1.f : 0.f);
}

// ======= bf16 mma.sync GEMM: C[rows x 1024] = sum_seg Aseg @ Bseg^T =======
// CTA tile 128x128, Kt=32, 4-stage cp.async multistage, 4 warps (2M x 2N),
// warp tile 64x64, mma.m16n8k16 bf16.
// sel: 0=E(2seg,full store), 1=Aea+P (bx<8: masked->g_Asel; else full->g_P),
//      3=D(3seg, masked->g_Dsel)
#define ROWB 80                  // padded smem row stride in bytes
#define STAGEB (2*128*ROWB)      // A+B per stage = 20480
extern __shared__ unsigned char dyn_smem[];

__global__ __launch_bounds__(128)
void mma_gemm_k(int sel) {
    const __nv_bfloat16 *A0, *A1, *A2 = nullptr;
    const __nv_bfloat16 *B0, *B1, *B2 = nullptr;
    float* C;
    int nseg;
    int masked = 0;              // masked per-class store into single slab
    int bx = blockIdx.x;
    size_t nBase;
    if (sel == 0) {
        A0 = A1 = g_emptyA; B0 = g_Bhi_empty; B1 = g_Blo_empty; C = g_E; nseg = 2;
        nBase = (size_t)bx * 128;
    } else if (sel == 1) {
        A0 = A1 = g_eachA; nseg = 2;
        if (bx < 8) { B0 = g_Bhi_each; B1 = g_Blo_each; C = g_Asel; masked = 1; nBase = (size_t)bx * 128; }
        else        { B0 = g_Bhi_not;  B1 = g_Blo_not;  C = g_P;    nBase = (size_t)(bx - 8) * 128; }
    } else {
        A0 = A1 = g_Xhi; A2 = g_Xlo;
        B0 = g_Bhi_not2; B1 = g_Blo_not2; B2 = g_Bhi_not2; C = g_Dsel; masked = 1; nseg = 3;
        nBase = (size_t)bx * 128;
    }

    const uint32_t sBase = smem_to_u32(dyn_smem);

    const int tid  = threadIdx.x;
    const int lane = tid & 31;
    const int wid  = tid >> 5;
    const int wm   = wid & 1;          // 2 warps along M
    const int wn   = wid >> 1;         // 2 warps along N
    const size_t mBase = (size_t)blockIdx.y * 128;

    const int NT = nseg * 32;          // 32 Kt-tiles per 1024-K segment

    // cp.async mapping: per matrix 512 16B-chunks; each thread loads 4
    const int rr = tid >> 2;           // base row (0..31), +32*i
    const int cc = tid & 3;            // 16B column chunk

    float acc[4][8][4];
#pragma unroll
    for (int i = 0; i < 4; i++)
#pragma unroll
        for (int j = 0; j < 8; j++)
#pragma unroll
            for (int q = 0; q < 4; q++) acc[i][j][q] = 0.f;

    auto issue_tile = [&](int t, int stage) {
        int seg = t >> 5, kk = (t & 31) * 32;
        const __nv_bfloat16* As = (seg == 0) ? A0 : ((seg == 1) ? A1 : A2);
        const __nv_bfloat16* Bs = (seg == 0) ? B0 : ((seg == 1) ? B1 : B2);
        uint32_t base = sBase + (uint32_t)stage * STAGEB;
#pragma unroll
        for (int i = 0; i < 4; i++) {
            int row = rr + i * 32;
            CP_ASYNC_16(base + row * ROWB + cc * 16,
                        As + (mBase + row) * 1024 + kk + cc * 8);
            CP_ASYNC_16(base + 128*ROWB + row * ROWB + cc * 16,
                        Bs + (nBase + row) * 1024 + kk + cc * 8);
        }
        CP_ASYNC_COMMIT();
    };

    issue_tile(0, 0);
    issue_tile(1, 1);
    issue_tile(2, 2);

    for (int t = 0; t < NT; ++t) {
        int w = NT - 1 - t;
        if (w >= 2)      { CP_ASYNC_WAIT_2(); }
        else if (w == 1) { CP_ASYNC_WAIT_1(); }
        else             { CP_ASYNC_WAIT_0(); }
        __syncthreads();

        uint32_t aB = sBase + (uint32_t)(t & 3) * STAGEB;
        uint32_t bB = aB + 128*ROWB;
#pragma unroll
        for (int ks = 0; ks < 2; ks++) {
            uint32_t afr[4][4];
#pragma unroll
            for (int mi = 0; mi < 4; mi++) {
                uint32_t addr = aB + (uint32_t)(wm * 64 + mi * 16 + (lane & 15)) * ROWB
                              + (uint32_t)(ks * 32 + (lane >> 4) * 16);
                LDSM_X4(afr[mi], addr);
            }
            uint32_t bfr[4][4];
#pragma unroll
            for (int nb = 0; nb < 4; nb++) {
                uint32_t addr = bB + (uint32_t)(wn * 64 + nb * 16 + (lane & 15)) * ROWB
                              + (uint32_t)(ks * 32 + (lane >> 4) * 16);
                LDSM_X4(bfr[nb], addr);
            }
#pragma unroll
            for (int mi = 0; mi < 4; mi++)
#pragma unroll
                for (int j = 0; j < 8; j++) {
                    int nb = j >> 1, h = j & 1;
                    mma_16816_bf16(acc[mi][j], afr[mi], bfr[nb][h], bfr[nb][h + 2]);
                }
        }
        if (t + 3 < NT) issue_tile(t + 3, (t + 3) & 3);
    }

    // ---- epilogue ----
    const int g  = lane >> 2;
    const int t2 = (lane & 3) * 2;
    if (!masked) {
#pragma unroll
        for (int mi = 0; mi < 4; mi++)
#pragma unroll
            for (int j = 0; j < 8; j++) {
                size_t r = mBase + (size_t)(wm * 64 + mi * 16 + g);
                size_t c = nBase + (size_t)(wn * 64 + j * 8 + t2);
                *(float2*)&C[r * 1024 + c]       = make_float2(acc[mi][j][0], acc[mi][j][1]);
                *(float2*)&C[(r + 8) * 1024 + c] = make_float2(acc[mi][j][2], acc[mi][j][3]);
            }
    } else {
#pragma unroll
        for (int mi = 0; mi < 4; mi++)
#pragma unroll
            for (int j = 0; j < 8; j++) {
                size_t r = mBase + (size_t)(wm * 64 + mi * 16 + g);
                size_t c = nBase + (size_t)(wn * 64 + j * 8 + t2);
                int k1 = (int)(r >> 12) + 1;          // slab -> class id
                {
                    size_t b = r & 4095;
                    size_t e = b * 1024 + c;
                    if (g_cls[e]     == k1) C[e]     = acc[mi][j][0];
                    if (g_cls[e + 1] == k1) C[e + 1] = acc[mi][j][1];
                }
                {
                    size_t b = (r + 8) & 4095;
                    size_t e = b * 1024 + c;
                    if (g_cls[e]     == k1) C[e]     = acc[mi][j][2];
                    if (g_cls[e + 1] == k1) C[e + 1] = acc[mi][j][3];
                }
            }
    }
}

// ======= init (fused): N_k = T - P_k; a,s; X_k = N_k * s split to bf16 =======
__global__ void init_k() {
    int idx = blockIdx.x * blockDim.x + threadIdx.x;
    if (idx >= KSTRIDE) return;
    float P0 = g_P[0*KSTRIDE + idx];
    float P1 = g_P[1*KSTRIDE + idx];
    float P2 = g_P[2*KSTRIDE + idx];
    float P3 = g_P[3*KSTRIDE + idx];
    float T = P0 + P1 + P2 + P3;
    float N0 = T - P0, N1 = T - P1, N2 = T - P2, N3 = T - P3;
    g_N[0*KSTRIDE + idx] = N0;
    g_N[1*KSTRIDE + idx] = N1;
    g_N[2*KSTRIDE + idx] = N2;
    g_N[3*KSTRIDE + idx] = N3;
    int c = g_cls[idx];
    float a = 0.f, s = 0.5f;
    if (c != 0) {
        int k = c - 1;
        float Nk = (k == 0) ? N0 : (k == 1) ? N1 : (k == 2) ? N2 : N3;
        a = g_Asel[idx] + g_E[idx] - Nk;
        s = 1.f / (1.f + expf(-a));
    }
    g_a[idx] = a;
    g_s[idx] = s;
    float Nv[4] = {N0, N1, N2, N3};
#pragma unroll
    for (int k = 0; k < 4; k++) {
        float x = Nv[k] * s;
        __nv_bfloat16 h = __float2bfloat16(x);
        g_Xhi[k*KSTRIDE + idx] = h;
        g_Xlo[k*KSTRIDE + idx] = __float2bfloat16(x - __bfloat162float(h));
    }
}

// ======= update (fused): a += E + Dsel; s; optionally X = N*s for next depth =======
__global__ void update_k(int write_x) {
    int idx = blockIdx.x * blockDim.x + threadIdx.x;
    if (idx >= KSTRIDE) return;
    int c = g_cls[idx];
    float s = 0.5f;
    if (c != 0) {
        float a = g_a[idx] + g_E[idx] + g_Dsel[idx];
        s = 1.f / (1.f + expf(-a));
        if (write_x) g_a[idx] = a;
        else         g_s[idx] = s;     // final depth: publish s for the MLP
    }
    if (write_x) {
#pragma unroll
        for (int k = 0; k < 4; k++) {
            float x = g_N[k*KSTRIDE + idx] * s;
            __nv_bfloat16 h = __float2bfloat16(x);
            g_Xhi[k*KSTRIDE + idx] = h;
            g_Xlo[k*KSTRIDE + idx] = __float2bfloat16(x - __bfloat162float(h));
        }
    }
}

// ======= MLP head =======
__global__ __launch_bounds__(256)
void mlp1_k(const float* __restrict__ W1) {
    __shared__ float sS[64][65];
    __shared__ float sW[100][65];
    int tid = threadIdx.x;
    int rowBase = blockIdx.x * 64;
    float acc[25];
#pragma unroll
    for (int i = 0; i < 25; i++) acc[i] = 0.f;
    int r = tid >> 2, cs = (tid & 3) * 25;
    for (int k0 = 0; k0 < 1024; k0 += 64) {
#pragma unroll
        for (int i = 0; i < 16; i++) {
            int e = tid + i * 256; int rr = e >> 6, c = e & 63;
            sS[rr][c] = g_s[(size_t)(rowBase + rr) * 1024 + k0 + c];
        }
#pragma unroll
        for (int i = 0; i < 25; i++) {
            int e = tid + i * 256; int j = e >> 6, c = e & 63;
            sW[j][c] = W1[(size_t)j * 1024 + k0 + c];
        }
        __syncthreads();
#pragma unroll 8
        for (int k = 0; k < 64; k++) {
            float sv = sS[r][k];
#pragma unroll
            for (int j = 0; j < 25; j++) acc[j] += sv * sW[cs + j][k];
        }
        __syncthreads();
    }
#pragma unroll
    for (int j = 0; j < 25; j++) {
        float v = acc[j];
        g_x1[(size_t)(rowBase + r) * 100 + cs + j] = (v > 0.f) ? v : 0.2f * v;
    }
}

__global__ void mlp2_k(const float* __restrict__ W2) {
    int gw = (blockIdx.x * blockDim.x + threadIdx.x) >> 5;
    int lane = threadIdx.x & 31;
    if (gw >= BATCH * 100) return;
    int b = gw / 100, j = gw % 100;
    const float* xrow = g_x1 + (size_t)b * 100;
    const float* wrow = W2 + (size_t)j * 100;
    float acc = 0.f;
    for (int t = lane; t < 100; t += 32) acc += xrow[t] * wrow[t];
#pragma unroll
    for (int o = 16; o; o >>= 1) acc += __shfl_xor_sync(0xffffffffu, acc, o);
    if (lane == 0) g_x2[b * 100 + j] = (acc > 0.f) ? acc : 0.2f * acc;
}

__global__ void mlp3_k(const float* __restrict__ W3, float* __restrict__ out) {
    int gw = (blockIdx.x * blockDim.x + threadIdx.x) >> 5;
    int lane = threadIdx.x & 31;
    if (gw >= BATCH) return;
    const float* xrow = g_x2 + (size_t)gw * 100;
    float acc = 0.f;
    for (int t = lane; t < 100; t += 32) acc += xrow[t] * W3[t];
#pragma unroll
    for (int o = 16; o; o >>= 1) acc += __shfl_xor_sync(0xffffffffu, acc, o);
    if (lane == 0) out[gw] = acc;
}

// ======= launch =======
extern "C" void kernel_launch(void* const* d_in, const int* in_sizes, int n_in,
                              void* d_out, int out_size) {
    (void)in_sizes; (void)n_in; (void)out_size;
    const int*   dots    = (const int*)d_in[0];
    const float* w_each  = (const float*)d_in[1];
    const float* w_not   = (const float*)d_in[2];
    const float* w_not2  = (const float*)d_in[3];
    const float* w_empty = (const float*)d_in[4];
    const float* W1      = (const float*)d_in[5];
    const float* W2      = (const float*)d_in[6];
    const float* W3      = (const float*)d_in[7];
    float* out = (float*)d_out;

    const int SMEM = 4 * STAGEB;   // 81920
    cudaFuncSetAttribute(mma_gemm_k, cudaFuncAttributeMaxDynamicSharedMemorySize, SMEM);

    build_B_k<<<(CELLS*CELLS + 255)/256, 256>>>(w_each, w_not, w_not2, w_empty);
    build_masks_k<<<(KSTRIDE + 255)/256, 256>>>(dots);

    mma_gemm_k<<<dim3(8, 32),   128, SMEM>>>(0);   // E
    mma_gemm_k<<<dim3(16, 128), 128, SMEM>>>(1);   // Aea(masked) + P

    init_k<<<(KSTRIDE + 255)/256, 256>>>();

    for (int d = 0; d < 4; d++) {
        mma_gemm_k<<<dim3(8, 128), 128, SMEM>>>(3);   // D (3-term split, masked)
        update_k<<<(KSTRIDE + 255)/256, 256>>>(d < 3 ? 1 : 0);
    }

    mlp1_k<<<BATCH/64, 256>>>(W1);
    {
        long nw = (long)BATCH * 100 * 32;
        mlp2_k<<<(unsigned)((nw + 255)/256), 256>>>(W2);
        long nw3 = (long)BATCH * 32;
        mlp3_k<<<(unsigned)((nw3 + 255)/256), 256>>>(W3, out);
    }
}

// round 14
// speedup vs baseline: 2.7082x; 1.1737x over previous
#include <cuda_runtime.h>
#include <cuda_bf16.h>
#include <math.h>
#include <stdint.h>

#define BATCH 4096
#define CELLS 1024
#define KSTRIDE (BATCH*CELLS)   // 4194304 elements per (k) slab

// ======================= helpers (baseline PTX only) =======================
__device__ __forceinline__ uint32_t smem_to_u32(const void* smem_ptr) {
    uint32_t addr;
    asm("{ .reg .u64 tmp; cvta.to.shared.u64 tmp, %1; cvt.u32.u64 %0, tmp; }"
        : "=r"(addr) : "l"(smem_ptr));
    return addr;
}
#define LDSM_X4(r, addr) \
    asm volatile("ldmatrix.sync.aligned.m8n8.x4.shared.b16 {%0,%1,%2,%3}, [%4];" \
        : "=r"((r)[0]), "=r"((r)[1]), "=r"((r)[2]), "=r"((r)[3]) : "r"(addr))
#define CP_ASYNC_16(dst, src) \
    asm volatile("cp.async.cg.shared.global [%0], [%1], 16;" :: "r"(dst), "l"(src) : "memory")
#define CP_ASYNC_COMMIT() asm volatile("cp.async.commit_group;" ::: "memory")
#define CP_ASYNC_WAIT_1() asm volatile("cp.async.wait_group 1;" ::: "memory")
#define CP_ASYNC_WAIT_0() asm volatile("cp.async.wait_group 0;" ::: "memory")

__device__ __forceinline__ void mma_16816_bf16(float* c, const uint32_t* a,
                                               uint32_t b0, uint32_t b1) {
    asm volatile(
        "mma.sync.aligned.m16n8k16.row.col.f32.bf16.bf16.f32 "
        "{%0,%1,%2,%3}, {%4,%5,%6,%7}, {%8,%9}, {%0,%1,%2,%3};"
        : "+f"(c[0]), "+f"(c[1]), "+f"(c[2]), "+f"(c[3])
        : "r"(a[0]), "r"(a[1]), "r"(a[2]), "r"(a[3]), "r"(b0), "r"(b1));
}

// smem tile: 128 rows x 32 cols bf16 = 8KB, row = 64B = 4 chunks of 16B.
// XOR swizzle: physical chunk = c ^ ((row>>1)&3). Conflict-free for ldmatrix:
// per 8-row phase, even rows cover banks 0-15, odd rows banks 16-31.
__device__ __forceinline__ uint32_t swz(uint32_t row, uint32_t c) {
    return row * 64u + ((c ^ ((row >> 1) & 3u)) * 16u);
}

// ======================= device global scratch =======================
__device__ __nv_bfloat16 g_Bhi_empty[CELLS*CELLS];
__device__ __nv_bfloat16 g_Blo_empty[CELLS*CELLS];
__device__ __nv_bfloat16 g_Bhi_each [CELLS*CELLS];
__device__ __nv_bfloat16 g_Blo_each [CELLS*CELLS];
__device__ __nv_bfloat16 g_Bhi_not  [CELLS*CELLS];
__device__ __nv_bfloat16 g_Blo_not  [CELLS*CELLS];
__device__ __nv_bfloat16 g_Bhi_not2 [CELLS*CELLS];
__device__ __nv_bfloat16 g_Blo_not2 [CELLS*CELLS];

__device__ __nv_bfloat16 g_emptyA[KSTRIDE];       // exact 0/1 masks in bf16
__device__ __nv_bfloat16 g_eachA [4*KSTRIDE];
__device__ __nv_bfloat16 g_Xhi   [4*KSTRIDE];     // split of X = N*s
__device__ __nv_bfloat16 g_Xlo   [4*KSTRIDE];

__device__ float g_E   [KSTRIDE];
__device__ float g_P   [4*KSTRIDE];
__device__ float g_N   [4*KSTRIDE];
__device__ float g_Asel[KSTRIDE];    // Aea masked to own class, single slab
__device__ float g_Dsel[KSTRIDE];    // D masked to own class, single slab
__device__ float g_a   [KSTRIDE];
__device__ float g_s   [KSTRIDE];
__device__ unsigned char g_cls[KSTRIDE];
__device__ float g_x1[BATCH*100];
__device__ float g_x2[BATCH*100];

// ======= build transposed conv matrices, split to bf16 hi/lo =======
__global__ void build_B_k(const float* __restrict__ w_each,
                          const float* __restrict__ w_not,
                          const float* __restrict__ w_not2,
                          const float* __restrict__ w_empty) {
    int idx = blockIdx.x * blockDim.x + threadIdx.x;
    if (idx >= CELLS*CELLS) return;
    int n = idx >> 10;      // output cell (row of B)
    int k = idx & 1023;     // input cell  (col of B)
    int ny = n >> 5, nx = n & 31;
    int kv = k >> 5, kh = k & 31;
    int dy = kv - ny + 16, dx = kh - nx + 16;
    float we = 0.f, wa = 0.f, wn = 0.f, w2 = 0.f;
    if ((unsigned)dy < 33u && (unsigned)dx < 33u) {
        int wi = dy * 33 + dx;
        we = w_empty[wi]; wa = w_each[wi]; wn = w_not[wi]; w2 = w_not2[wi];
    }
    __nv_bfloat16 h;
    h = __float2bfloat16(we); g_Bhi_empty[idx] = h; g_Blo_empty[idx] = __float2bfloat16(we - __bfloat162float(h));
    h = __float2bfloat16(wa); g_Bhi_each [idx] = h; g_Blo_each [idx] = __float2bfloat16(wa - __bfloat162float(h));
    h = __float2bfloat16(wn); g_Bhi_not  [idx] = h; g_Blo_not  [idx] = __float2bfloat16(wn - __bfloat162float(h));
    h = __float2bfloat16(w2); g_Bhi_not2 [idx] = h; g_Blo_not2 [idx] = __float2bfloat16(w2 - __bfloat162float(h));
}

// ======= masks (bf16, exact 0/1) =======
__global__ void build_masks_k(const int* __restrict__ dots) {
    int idx = blockIdx.x * blockDim.x + threadIdx.x;
    if (idx >= KSTRIDE) return;
    int b = idx >> 10;
    int i = idx & 1023;
    int c = dots[i * BATCH + b];   // dots[(v*32+h)*B + b]
    g_cls[idx] = (unsigned char)c;
    g_emptyA[idx] = __float2bfloat16((c == 0) ? 1.f : 0.f);
#pragma unroll
    for (int k = 0; k < 4; k++)
        g_eachA[k*KSTRIDE + idx] = __float2bfloat16((c == k + 1) ? 1.f : 0.f);
}

// ======= bf16 mma.sync GEMM with interleaved K-segments =======
// CTA tile 128x128, Kt=32, 32 k-tiles; per tile load {A0[,A1],Bhi,Blo} once and
// run the hi/lo compensation passes in-place:
//   phase A (exact A): acc += A@Bhi + A@Blo          (2 passes)
//   diffusion:         acc += Ahi@Bhi + Ahi@Blo + Alo@Bhi   (3 passes)
// 4 warps (2M x 2N), warp tile 64x64, 3-stage cp.async, swizzled 8KB tiles.
#define TILEB 8192
#define STAGEB (4*TILEB)         // A0,A1,B0,B1 slots = 32KB
extern __shared__ unsigned char dyn_smem[];

__global__ __launch_bounds__(128)
void mma_gemm_k(int sel) {
    const __nv_bfloat16 *A0, *A1 = nullptr;
    const __nv_bfloat16 *B0, *B1;
    float* C;
    int npass;                   // 2 or 3
    int masked = 0;
    int bx = blockIdx.x;
    size_t nBase;
    if (sel == 0) {
        A0 = g_emptyA; B0 = g_Bhi_empty; B1 = g_Blo_empty; C = g_E; npass = 2;
        nBase = (size_t)bx * 128;
    } else if (sel == 1) {
        A0 = g_eachA; npass = 2;
        if (bx < 8) { B0 = g_Bhi_each; B1 = g_Blo_each; C = g_Asel; masked = 1; nBase = (size_t)bx * 128; }
        else        { B0 = g_Bhi_not;  B1 = g_Blo_not;  C = g_P;    nBase = (size_t)(bx - 8) * 128; }
    } else {
        A0 = g_Xhi; A1 = g_Xlo;
        B0 = g_Bhi_not2; B1 = g_Blo_not2; C = g_Dsel; masked = 1; npass = 3;
        nBase = (size_t)bx * 128;
    }

    const uint32_t sBase = smem_to_u32(dyn_smem);

    const int tid  = threadIdx.x;
    const int lane = tid & 31;
    const int wid  = tid >> 5;
    const int wm   = wid & 1;          // 2 warps along M
    const int wn   = wid >> 1;         // 2 warps along N
    const size_t mBase = (size_t)blockIdx.y * 128;

    const int NT = 32;                 // 32 k-tiles cover K=1024

    // cp.async mapping: per tile 512 16B-chunks; thread loads 4 (rows rr+32i, chunk cc)
    const int rr = tid >> 2;
    const int cc = tid & 3;

    float acc[4][8][4];
#pragma unroll
    for (int i = 0; i < 4; i++)
#pragma unroll
        for (int j = 0; j < 8; j++)
#pragma unroll
            for (int q = 0; q < 4; q++) acc[i][j][q] = 0.f;

    auto load_tile = [&](uint32_t dstBase, const __nv_bfloat16* src, size_t rowBase, int kk) {
#pragma unroll
        for (int i = 0; i < 4; i++) {
            uint32_t row = (uint32_t)(rr + i * 32);
            CP_ASYNC_16(dstBase + swz(row, (uint32_t)cc),
                        src + (rowBase + row) * 1024 + kk + cc * 8);
        }
    };
    auto issue_tile = [&](int t, int stage) {
        int kk = t * 32;
        uint32_t base = sBase + (uint32_t)stage * STAGEB;
        load_tile(base,             A0, mBase, kk);
        if (npass == 3) load_tile(base + TILEB, A1, mBase, kk);
        load_tile(base + 2*TILEB,   B0, nBase, kk);
        load_tile(base + 3*TILEB,   B1, nBase, kk);
        CP_ASYNC_COMMIT();
    };

    issue_tile(0, 0);
    issue_tile(1, 1);

    int stage = 0;
    for (int t = 0; t < NT; ++t) {
        if (t < NT - 1) CP_ASYNC_WAIT_1();
        else            CP_ASYNC_WAIT_0();
        __syncthreads();

        uint32_t base = sBase + (uint32_t)stage * STAGEB;
#pragma unroll
        for (int ks = 0; ks < 2; ks++) {
            const uint32_t cA = (uint32_t)(ks * 2);      // chunk base for this k16 step
            uint32_t bfr0[4][4], bfr1[4][4], afr[4][4];
#pragma unroll
            for (int nb = 0; nb < 4; nb++) {
                uint32_t row = (uint32_t)(wn * 64 + nb * 16 + (lane & 15));
                uint32_t c   = cA + (uint32_t)(lane >> 4);
                LDSM_X4(bfr0[nb], base + 2*TILEB + swz(row, c));
                LDSM_X4(bfr1[nb], base + 3*TILEB + swz(row, c));
            }
#pragma unroll
            for (int mi = 0; mi < 4; mi++) {
                uint32_t row = (uint32_t)(wm * 64 + mi * 16 + (lane & 15));
                uint32_t c   = cA + (uint32_t)(lane >> 4);
                LDSM_X4(afr[mi], base + swz(row, c));
            }
            // pass 1: A0 @ Bhi
#pragma unroll
            for (int mi = 0; mi < 4; mi++)
#pragma unroll
                for (int j = 0; j < 8; j++) {
                    int nb = j >> 1, h = j & 1;
                    mma_16816_bf16(acc[mi][j], afr[mi], bfr0[nb][h], bfr0[nb][h + 2]);
                }
            // pass 2: A0 @ Blo
#pragma unroll
            for (int mi = 0; mi < 4; mi++)
#pragma unroll
                for (int j = 0; j < 8; j++) {
                    int nb = j >> 1, h = j & 1;
                    mma_16816_bf16(acc[mi][j], afr[mi], bfr1[nb][h], bfr1[nb][h + 2]);
                }
            if (npass == 3) {
                // pass 3: A1 (lo) @ Bhi — reuse afr registers
#pragma unroll
                for (int mi = 0; mi < 4; mi++) {
                    uint32_t row = (uint32_t)(wm * 64 + mi * 16 + (lane & 15));
                    uint32_t c   = cA + (uint32_t)(lane >> 4);
                    LDSM_X4(afr[mi], base + TILEB + swz(row, c));
                }
#pragma unroll
                for (int mi = 0; mi < 4; mi++)
#pragma unroll
                    for (int j = 0; j < 8; j++) {
                        int nb = j >> 1, h = j & 1;
                        mma_16816_bf16(acc[mi][j], afr[mi], bfr0[nb][h], bfr0[nb][h + 2]);
                    }
            }
        }
        if (t + 2 < NT) {
            int s2 = stage + 2; if (s2 >= 3) s2 -= 3;
            issue_tile(t + 2, s2);
        }
        if (++stage == 3) stage = 0;
    }

    // ---- epilogue ----
    const int g  = lane >> 2;
    const int t2 = (lane & 3) * 2;
    if (!masked) {
#pragma unroll
        for (int mi = 0; mi < 4; mi++)
#pragma unroll
            for (int j = 0; j < 8; j++) {
                size_t r = mBase + (size_t)(wm * 64 + mi * 16 + g);
                size_t c = nBase + (size_t)(wn * 64 + j * 8 + t2);
                *(float2*)&C[r * 1024 + c]       = make_float2(acc[mi][j][0], acc[mi][j][1]);
                *(float2*)&C[(r + 8) * 1024 + c] = make_float2(acc[mi][j][2], acc[mi][j][3]);
            }
    } else {
#pragma unroll
        for (int mi = 0; mi < 4; mi++)
#pragma unroll
            for (int j = 0; j < 8; j++) {
                size_t r = mBase + (size_t)(wm * 64 + mi * 16 + g);
                size_t c = nBase + (size_t)(wn * 64 + j * 8 + t2);
                int k1 = (int)(r >> 12) + 1;          // slab -> class id
                {
                    size_t b = r & 4095;
                    size_t e = b * 1024 + c;
                    if (g_cls[e]     == k1) C[e]     = acc[mi][j][0];
                    if (g_cls[e + 1] == k1) C[e + 1] = acc[mi][j][1];
                }
                {
                    size_t b = (r + 8) & 4095;
                    size_t e = b * 1024 + c;
                    if (g_cls[e]     == k1) C[e]     = acc[mi][j][2];
                    if (g_cls[e + 1] == k1) C[e + 1] = acc[mi][j][3];
                }
            }
    }
}

// ======= init (fused): N_k = T - P_k; a,s; X_k = N_k * s split to bf16 =======
__global__ void init_k() {
    int idx = blockIdx.x * blockDim.x + threadIdx.x;
    if (idx >= KSTRIDE) return;
    float P0 = g_P[0*KSTRIDE + idx];
    float P1 = g_P[1*KSTRIDE + idx];
    float P2 = g_P[2*KSTRIDE + idx];
    float P3 = g_P[3*KSTRIDE + idx];
    float T = P0 + P1 + P2 + P3;
    float N0 = T - P0, N1 = T - P1, N2 = T - P2, N3 = T - P3;
    g_N[0*KSTRIDE + idx] = N0;
    g_N[1*KSTRIDE + idx] = N1;
    g_N[2*KSTRIDE + idx] = N2;
    g_N[3*KSTRIDE + idx] = N3;
    int c = g_cls[idx];
    float a = 0.f, s = 0.5f;
    if (c != 0) {
        int k = c - 1;
        float Nk = (k == 0) ? N0 : (k == 1) ? N1 : (k == 2) ? N2 : N3;
        a = g_Asel[idx] + g_E[idx] - Nk;
        s = 1.f / (1.f + expf(-a));
    }
    g_a[idx] = a;
    g_s[idx] = s;
    float Nv[4] = {N0, N1, N2, N3};
#pragma unroll
    for (int k = 0; k < 4; k++) {
        float x = Nv[k] * s;
        __nv_bfloat16 h = __float2bfloat16(x);
        g_Xhi[k*KSTRIDE + idx] = h;
        g_Xlo[k*KSTRIDE + idx] = __float2bfloat16(x - __bfloat162float(h));
    }
}

// ======= update (fused): a += E + Dsel; s; optionally X = N*s for next depth =======
__global__ void update_k(int write_x) {
    int idx = blockIdx.x * blockDim.x + threadIdx.x;
    if (idx >= KSTRIDE) return;
    int c = g_cls[idx];
    float s = 0.5f;
    if (c != 0) {
        float a = g_a[idx] + g_E[idx] + g_Dsel[idx];
        s = 1.f / (1.f + expf(-a));
        if (write_x) g_a[idx] = a;
        else         g_s[idx] = s;     // final depth: publish s for the MLP
    }
    if (write_x) {
#pragma unroll
        for (int k = 0; k < 4; k++) {
            float x = g_N[k*KSTRIDE + idx] * s;
            __nv_bfloat16 h = __float2bfloat16(x);
            g_Xhi[k*KSTRIDE + idx] = h;
            g_Xlo[k*KSTRIDE + idx] = __float2bfloat16(x - __bfloat162float(h));
        }
    }
}

// ======= MLP head =======
__global__ __launch_bounds__(256)
void mlp1_k(const float* __restrict__ W1) {
    __shared__ float sS[64][65];
    __shared__ float sW[100][65];
    int tid = threadIdx.x;
    int rowBase = blockIdx.x * 64;
    float acc[25];
#pragma unroll
    for (int i = 0; i < 25; i++) acc[i] = 0.f;
    int r = tid >> 2, cs = (tid & 3) * 25;
    for (int k0 = 0; k0 < 1024; k0 += 64) {
#pragma unroll
        for (int i = 0; i < 16; i++) {
            int e = tid + i * 256; int rr = e >> 6, c = e & 63;
            sS[rr][c] = g_s[(size_t)(rowBase + rr) * 1024 + k0 + c];
        }
#pragma unroll
        for (int i = 0; i < 25; i++) {
            int e = tid + i * 256; int j = e >> 6, c = e & 63;
            sW[j][c] = W1[(size_t)j * 1024 + k0 + c];
        }
        __syncthreads();
#pragma unroll 8
        for (int k = 0; k < 64; k++) {
            float sv = sS[r][k];
#pragma unroll
            for (int j = 0; j < 25; j++) acc[j] += sv * sW[cs + j][k];
        }
        __syncthreads();
    }
#pragma unroll
    for (int j = 0; j < 25; j++) {
        float v = acc[j];
        g_x1[(size_t)(rowBase + r) * 100 + cs + j] = (v > 0.f) ? v : 0.2f * v;
    }
}

__global__ void mlp2_k(const float* __restrict__ W2) {
    int gw = (blockIdx.x * blockDim.x + threadIdx.x) >> 5;
    int lane = threadIdx.x & 31;
    if (gw >= BATCH * 100) return;
    int b = gw / 100, j = gw % 100;
    const float* xrow = g_x1 + (size_t)b * 100;
    const float* wrow = W2 + (size_t)j * 100;
    float acc = 0.f;
    for (int t = lane; t < 100; t += 32) acc += xrow[t] * wrow[t];
#pragma unroll
    for (int o = 16; o; o >>= 1) acc += __shfl_xor_sync(0xffffffffu, acc, o);
    if (lane == 0) g_x2[b * 100 + j] = (acc > 0.f) ? acc : 0.2f * acc;
}

__global__ void mlp3_k(const float* __restrict__ W3, float* __restrict__ out) {
    int gw = (blockIdx.x * blockDim.x + threadIdx.x) >> 5;
    int lane = threadIdx.x & 31;
    if (gw >= BATCH) return;
    const float* xrow = g_x2 + (size_t)gw * 100;
    float acc = 0.f;
    for (int t = lane; t < 100; t += 32) acc += xrow[t] * W3[t];
#pragma unroll
    for (int o = 16; o; o >>= 1) acc += __shfl_xor_sync(0xffffffffu, acc, o);
    if (lane == 0) out[gw] = acc;
}

// ======= launch =======
extern "C" void kernel_launch(void* const* d_in, const int* in_sizes, int n_in,
                              void* d_out, int out_size) {
    (void)in_sizes; (void)n_in; (void)out_size;
    const int*   dots    = (const int*)d_in[0];
    const float* w_each  = (const float*)d_in[1];
    const float* w_not   = (const float*)d_in[2];
    const float* w_not2  = (const float*)d_in[3];
    const float* w_empty = (const float*)d_in[4];
    const float* W1      = (const float*)d_in[5];
    const float* W2      = (const float*)d_in[6];
    const float* W3      = (const float*)d_in[7];
    float* out = (float*)d_out;

    const int SMEM = 3 * STAGEB;   // 98304
    cudaFuncSetAttribute(mma_gemm_k, cudaFuncAttributeMaxDynamicSharedMemorySize, SMEM);

    build_B_k<<<(CELLS*CELLS + 255)/256, 256>>>(w_each, w_not, w_not2, w_empty);
    build_masks_k<<<(KSTRIDE + 255)/256, 256>>>(dots);

    mma_gemm_k<<<dim3(8, 32),   128, SMEM>>>(0);   // E
    mma_gemm_k<<<dim3(16, 128), 128, SMEM>>>(1);   // Aea(masked) + P

    init_k<<<(KSTRIDE + 255)/256, 256>>>();

    for (int d = 0; d < 4; d++) {
        mma_gemm_k<<<dim3(8, 128), 128, SMEM>>>(3);   // D (interleaved 3-pass, masked)
        update_k<<<(KSTRIDE + 255)/256, 256>>>(d < 3 ? 1 : 0);
    }

    mlp1_k<<<BATCH/64, 256>>>(W1);
    {
        long nw = (long)BATCH * 100 * 32;
        mlp2_k<<<(unsigned)((nw + 255)/256), 256>>>(W2);
        long nw3 = (long)BATCH * 32;
        mlp3_k<<<(unsigned)((nw3 + 255)/256), 256>>>(W3, out);
    }
}

// round 15
// speedup vs baseline: 2.8598x; 1.0560x over previous
#include <cuda_runtime.h>
#include <cuda_bf16.h>
#include <math.h>
#include <stdint.h>

#define BATCH 4096
#define CELLS 1024
#define KSTRIDE (BATCH*CELLS)   // 4194304 elements per (k) slab

// ======================= helpers (baseline PTX only) =======================
__device__ __forceinline__ uint32_t smem_to_u32(const void* smem_ptr) {
    uint32_t addr;
    asm("{ .reg .u64 tmp; cvta.to.shared.u64 tmp, %1; cvt.u32.u64 %0, tmp; }"
        : "=r"(addr) : "l"(smem_ptr));
    return addr;
}
#define LDSM_X4(r, addr) \
    asm volatile("ldmatrix.sync.aligned.m8n8.x4.shared.b16 {%0,%1,%2,%3}, [%4];" \
        : "=r"((r)[0]), "=r"((r)[1]), "=r"((r)[2]), "=r"((r)[3]) : "r"(addr))
#define CP_ASYNC_16(dst, src) \
    asm volatile("cp.async.cg.shared.global [%0], [%1], 16;" :: "r"(dst), "l"(src) : "memory")
#define CP_ASYNC_COMMIT() asm volatile("cp.async.commit_group;" ::: "memory")
#define CP_ASYNC_WAIT_1() asm volatile("cp.async.wait_group 1;" ::: "memory")
#define CP_ASYNC_WAIT_0() asm volatile("cp.async.wait_group 0;" ::: "memory")

__device__ __forceinline__ void mma_16816_bf16(float* c, const uint32_t* a,
                                               uint32_t b0, uint32_t b1) {
    asm volatile(
        "mma.sync.aligned.m16n8k16.row.col.f32.bf16.bf16.f32 "
        "{%0,%1,%2,%3}, {%4,%5,%6,%7}, {%8,%9}, {%0,%1,%2,%3};"
        : "+f"(c[0]), "+f"(c[1]), "+f"(c[2]), "+f"(c[3])
        : "r"(a[0]), "r"(a[1]), "r"(a[2]), "r"(a[3]), "r"(b0), "r"(b1));
}

// smem tile: 128 rows x 32 cols bf16 = 8KB, row = 64B = 4 chunks of 16B.
// XOR swizzle: physical chunk = c ^ ((row>>1)&3). Conflict-free for ldmatrix.
__device__ __forceinline__ uint32_t swz(uint32_t row, uint32_t c) {
    return row * 64u + ((c ^ ((row >> 1) & 3u)) * 16u);
}

// ======================= device global scratch =======================
__device__ __nv_bfloat16 g_Bhi_empty[CELLS*CELLS];
__device__ __nv_bfloat16 g_Blo_empty[CELLS*CELLS];
__device__ __nv_bfloat16 g_Bhi_each [CELLS*CELLS];
__device__ __nv_bfloat16 g_Blo_each [CELLS*CELLS];
__device__ __nv_bfloat16 g_Bhi_not  [CELLS*CELLS];
__device__ __nv_bfloat16 g_Blo_not  [CELLS*CELLS];
__device__ __nv_bfloat16 g_Bhi_not2 [CELLS*CELLS];
__device__ __nv_bfloat16 g_Blo_not2 [CELLS*CELLS];

__device__ __nv_bfloat16 g_emptyA[KSTRIDE];       // exact 0/1 masks in bf16
__device__ __nv_bfloat16 g_eachA [4*KSTRIDE];
__device__ __nv_bfloat16 g_Xhi   [4*KSTRIDE];     // split of X = N*s
__device__ __nv_bfloat16 g_Xlo   [4*KSTRIDE];

__device__ float g_E   [KSTRIDE];
__device__ float g_P   [4*KSTRIDE];
__device__ float g_N   [4*KSTRIDE];
__device__ float g_Asel[KSTRIDE];    // Aea masked to own class, single slab
__device__ float g_Dsel[KSTRIDE];    // D masked to own class, single slab
__device__ float g_a   [KSTRIDE];
__device__ float g_s   [KSTRIDE];
__device__ unsigned char g_cls[KSTRIDE];
__device__ float g_x1[BATCH*100];
__device__ float g_x2[BATCH*100];

// ======= build transposed conv matrices, split to bf16 hi/lo =======
__global__ void build_B_k(const float* __restrict__ w_each,
                          const float* __restrict__ w_not,
                          const float* __restrict__ w_not2,
                          const float* __restrict__ w_empty) {
    int idx = blockIdx.x * blockDim.x + threadIdx.x;
    if (idx >= CELLS*CELLS) return;
    int n = idx >> 10;      // output cell (row of B)
    int k = idx & 1023;     // input cell  (col of B)
    int ny = n >> 5, nx = n & 31;
    int kv = k >> 5, kh = k & 31;
    int dy = kv - ny + 16, dx = kh - nx + 16;
    float we = 0.f, wa = 0.f, wn = 0.f, w2 = 0.f;
    if ((unsigned)dy < 33u && (unsigned)dx < 33u) {
        int wi = dy * 33 + dx;
        we = w_empty[wi]; wa = w_each[wi]; wn = w_not[wi]; w2 = w_not2[wi];
    }
    __nv_bfloat16 h;
    h = __float2bfloat16(we); g_Bhi_empty[idx] = h; g_Blo_empty[idx] = __float2bfloat16(we - __bfloat162float(h));
    h = __float2bfloat16(wa); g_Bhi_each [idx] = h; g_Blo_each [idx] = __float2bfloat16(wa - __bfloat162float(h));
    h = __float2bfloat16(wn); g_Bhi_not  [idx] = h; g_Blo_not  [idx] = __float2bfloat16(wn - __bfloat162float(h));
    h = __float2bfloat16(w2); g_Bhi_not2 [idx] = h; g_Blo_not2 [idx] = __float2bfloat16(w2 - __bfloat162float(h));
}

// ======= masks (bf16, exact 0/1) =======
__global__ void build_masks_k(const int* __restrict__ dots) {
    int idx = blockIdx.x * blockDim.x + threadIdx.x;
    if (idx >= KSTRIDE) return;
    int b = idx >> 10;
    int i = idx & 1023;
    int c = dots[i * BATCH + b];   // dots[(v*32+h)*B + b]
    g_cls[idx] = (unsigned char)c;
    g_emptyA[idx] = __float2bfloat16((c == 0) ? 1.f : 0.f);
#pragma unroll
    for (int k = 0; k < 4; k++)
        g_eachA[k*KSTRIDE + idx] = __float2bfloat16((c == k + 1) ? 1.f : 0.f);
}

// ======= bf16 mma.sync GEMM with interleaved K-segments =======
// CTA tile 128x128, Kt=32, 32 k-tiles; per tile load {A0[,A1],Bhi,Blo} once and
// run hi/lo compensation passes in-place:
//   phase A (exact A): acc += A@Bhi + A@Blo                (2 passes)
//   diffusion:         acc += Ahi@Bhi + Ahi@Blo + Alo@Bhi  (3 passes)
// 8 warps (2M x 4N), warp tile 64x32, 3-stage cp.async, swizzled 8KB tiles.
#define TILEB 8192
#define STAGEB (4*TILEB)         // A0,A1,B0,B1 slots = 32KB
extern __shared__ unsigned char dyn_smem[];

__global__ __launch_bounds__(256, 2)
void mma_gemm_k(int sel) {
    const __nv_bfloat16 *A0, *A1 = nullptr;
    const __nv_bfloat16 *B0, *B1;
    float* C;
    int npass;                   // 2 or 3
    int masked = 0;
    int bx = blockIdx.x;
    size_t nBase;
    if (sel == 0) {
        A0 = g_emptyA; B0 = g_Bhi_empty; B1 = g_Blo_empty; C = g_E; npass = 2;
        nBase = (size_t)bx * 128;
    } else if (sel == 1) {
        A0 = g_eachA; npass = 2;
        if (bx < 8) { B0 = g_Bhi_each; B1 = g_Blo_each; C = g_Asel; masked = 1; nBase = (size_t)bx * 128; }
        else        { B0 = g_Bhi_not;  B1 = g_Blo_not;  C = g_P;    nBase = (size_t)(bx - 8) * 128; }
    } else {
        A0 = g_Xhi; A1 = g_Xlo;
        B0 = g_Bhi_not2; B1 = g_Blo_not2; C = g_Dsel; masked = 1; npass = 3;
        nBase = (size_t)bx * 128;
    }

    const uint32_t sBase = smem_to_u32(dyn_smem);

    const int tid  = threadIdx.x;
    const int lane = tid & 31;
    const int wid  = tid >> 5;
    const int wm   = wid & 1;          // 2 warps along M
    const int wn   = wid >> 1;         // 4 warps along N (32 cols each)
    const size_t mBase = (size_t)blockIdx.y * 128;

    const int NT = 32;                 // 32 k-tiles cover K=1024

    // cp.async: per tile 512 16B-chunks; thread loads 2 (rows rr, rr+64)
    const int rr = tid >> 2;
    const int cc = tid & 3;

    float acc[4][4][4];
#pragma unroll
    for (int i = 0; i < 4; i++)
#pragma unroll
        for (int j = 0; j < 4; j++)
#pragma unroll
            for (int q = 0; q < 4; q++) acc[i][j][q] = 0.f;

    auto load_tile = [&](uint32_t dstBase, const __nv_bfloat16* src, size_t rowBase, int kk) {
#pragma unroll
        for (int i = 0; i < 2; i++) {
            uint32_t row = (uint32_t)(rr + i * 64);
            CP_ASYNC_16(dstBase + swz(row, (uint32_t)cc),
                        src + (rowBase + row) * 1024 + kk + cc * 8);
        }
    };
    auto issue_tile = [&](int t, int stage) {
        int kk = t * 32;
        uint32_t base = sBase + (uint32_t)stage * STAGEB;
        load_tile(base,             A0, mBase, kk);
        if (npass == 3) load_tile(base + TILEB, A1, mBase, kk);
        load_tile(base + 2*TILEB,   B0, nBase, kk);
        load_tile(base + 3*TILEB,   B1, nBase, kk);
        CP_ASYNC_COMMIT();
    };

    issue_tile(0, 0);
    issue_tile(1, 1);

    int stage = 0;
    for (int t = 0; t < NT; ++t) {
        if (t < NT - 1) CP_ASYNC_WAIT_1();
        else            CP_ASYNC_WAIT_0();
        __syncthreads();

        uint32_t base = sBase + (uint32_t)stage * STAGEB;
#pragma unroll
        for (int ks = 0; ks < 2; ks++) {
            const uint32_t cA = (uint32_t)(ks * 2);      // 16B-chunk base of this k16
            uint32_t bfr0[2][4], bfr1[2][4], afr[4][4];
#pragma unroll
            for (int nb = 0; nb < 2; nb++) {
                uint32_t row = (uint32_t)(wn * 32 + nb * 16 + (lane & 15));
                uint32_t c   = cA + (uint32_t)(lane >> 4);
                LDSM_X4(bfr0[nb], base + 2*TILEB + swz(row, c));
                LDSM_X4(bfr1[nb], base + 3*TILEB + swz(row, c));
            }
#pragma unroll
            for (int mi = 0; mi < 4; mi++) {
                uint32_t row = (uint32_t)(wm * 64 + mi * 16 + (lane & 15));
                uint32_t c   = cA + (uint32_t)(lane >> 4);
                LDSM_X4(afr[mi], base + swz(row, c));
            }
            // pass 1: A0 @ Bhi
#pragma unroll
            for (int mi = 0; mi < 4; mi++)
#pragma unroll
                for (int j = 0; j < 4; j++) {
                    int nb = j >> 1, h = j & 1;
                    mma_16816_bf16(acc[mi][j], afr[mi], bfr0[nb][h], bfr0[nb][h + 2]);
                }
            // pass 2: A0 @ Blo
#pragma unroll
            for (int mi = 0; mi < 4; mi++)
#pragma unroll
                for (int j = 0; j < 4; j++) {
                    int nb = j >> 1, h = j & 1;
                    mma_16816_bf16(acc[mi][j], afr[mi], bfr1[nb][h], bfr1[nb][h + 2]);
                }
            if (npass == 3) {
                // pass 3: A1 (lo) @ Bhi — reuse afr registers
#pragma unroll
                for (int mi = 0; mi < 4; mi++) {
                    uint32_t row = (uint32_t)(wm * 64 + mi * 16 + (lane & 15));
                    uint32_t c   = cA + (uint32_t)(lane >> 4);
                    LDSM_X4(afr[mi], base + TILEB + swz(row, c));
                }
#pragma unroll
                for (int mi = 0; mi < 4; mi++)
#pragma unroll
                    for (int j = 0; j < 4; j++) {
                        int nb = j >> 1, h = j & 1;
                        mma_16816_bf16(acc[mi][j], afr[mi], bfr0[nb][h], bfr0[nb][h + 2]);
                    }
            }
        }
        if (t + 2 < NT) {
            int s2 = stage + 2; if (s2 >= 3) s2 -= 3;
            issue_tile(t + 2, s2);
        }
        if (++stage == 3) stage = 0;
    }

    // ---- epilogue ----
    const int g  = lane >> 2;
    const int t2 = (lane & 3) * 2;
    if (!masked) {
#pragma unroll
        for (int mi = 0; mi < 4; mi++)
#pragma unroll
            for (int j = 0; j < 4; j++) {
                size_t r = mBase + (size_t)(wm * 64 + mi * 16 + g);
                size_t c = nBase + (size_t)(wn * 32 + j * 8 + t2);
                *(float2*)&C[r * 1024 + c]       = make_float2(acc[mi][j][0], acc[mi][j][1]);
                *(float2*)&C[(r + 8) * 1024 + c] = make_float2(acc[mi][j][2], acc[mi][j][3]);
            }
    } else {
#pragma unroll
        for (int mi = 0; mi < 4; mi++)
#pragma unroll
            for (int j = 0; j < 4; j++) {
                size_t r = mBase + (size_t)(wm * 64 + mi * 16 + g);
                size_t c = nBase + (size_t)(wn * 32 + j * 8 + t2);
                int k1 = (int)(r >> 12) + 1;          // slab -> class id
                {
                    size_t b = r & 4095;
                    size_t e = b * 1024 + c;
                    if (g_cls[e]     == k1) C[e]     = acc[mi][j][0];
                    if (g_cls[e + 1] == k1) C[e + 1] = acc[mi][j][1];
                }
                {
                    size_t b = (r + 8) & 4095;
                    size_t e = b * 1024 + c;
                    if (g_cls[e]     == k1) C[e]     = acc[mi][j][2];
                    if (g_cls[e + 1] == k1) C[e + 1] = acc[mi][j][3];
                }
            }
    }
}

// ======= init (fused): N_k = T - P_k; a,s; X_k = N_k * s split to bf16 =======
__global__ void init_k() {
    int idx = blockIdx.x * blockDim.x + threadIdx.x;
    if (idx >= KSTRIDE) return;
    float P0 = g_P[0*KSTRIDE + idx];
    float P1 = g_P[1*KSTRIDE + idx];
    float P2 = g_P[2*KSTRIDE + idx];
    float P3 = g_P[3*KSTRIDE + idx];
    float T = P0 + P1 + P2 + P3;
    float N0 = T - P0, N1 = T - P1, N2 = T - P2, N3 = T - P3;
    g_N[0*KSTRIDE + idx] = N0;
    g_N[1*KSTRIDE + idx] = N1;
    g_N[2*KSTRIDE + idx] = N2;
    g_N[3*KSTRIDE + idx] = N3;
    int c = g_cls[idx];
    float a = 0.f, s = 0.5f;
    if (c != 0) {
        int k = c - 1;
        float Nk = (k == 0) ? N0 : (k == 1) ? N1 : (k == 2) ? N2 : N3;
        a = g_Asel[idx] + g_E[idx] - Nk;
        s = 1.f / (1.f + expf(-a));
    }
    g_a[idx] = a;
    g_s[idx] = s;
    float Nv[4] = {N0, N1, N2, N3};
#pragma unroll
    for (int k = 0; k < 4; k++) {
        float x = Nv[k] * s;
        __nv_bfloat16 h = __float2bfloat16(x);
        g_Xhi[k*KSTRIDE + idx] = h;
        g_Xlo[k*KSTRIDE + idx] = __float2bfloat16(x - __bfloat162float(h));
    }
}

// ======= update (fused): a += E + Dsel; s; optionally X = N*s for next depth =====
// Empty cells never change (a=0, s=0.5, X const from init) -> early exit.
__global__ void update_k(int write_x) {
    int idx = blockIdx.x * blockDim.x + threadIdx.x;
    if (idx >= KSTRIDE) return;
    int c = g_cls[idx];
    if (c == 0) return;
    float a = g_a[idx] + g_E[idx] + g_Dsel[idx];
    float s = 1.f / (1.f + expf(-a));
    if (write_x) {
        g_a[idx] = a;
#pragma unroll
        for (int k = 0; k < 4; k++) {
            float x = g_N[k*KSTRIDE + idx] * s;
            __nv_bfloat16 h = __float2bfloat16(x);
            g_Xhi[k*KSTRIDE + idx] = h;
            g_Xlo[k*KSTRIDE + idx] = __float2bfloat16(x - __bfloat162float(h));
        }
    } else {
        g_s[idx] = s;     // final depth: publish s for the MLP
    }
}

// ======= MLP head =======
__global__ __launch_bounds__(256)
void mlp1_k(const float* __restrict__ W1) {
    __shared__ float sS[64][65];
    __shared__ float sW[100][65];
    int tid = threadIdx.x;
    int rowBase = blockIdx.x * 64;
    float acc[25];
#pragma unroll
    for (int i = 0; i < 25; i++) acc[i] = 0.f;
    int r = tid >> 2, cs = (tid & 3) * 25;
    for (int k0 = 0; k0 < 1024; k0 += 64) {
#pragma unroll
        for (int i = 0; i < 16; i++) {
            int e = tid + i * 256; int rr = e >> 6, c = e & 63;
            sS[rr][c] = g_s[(size_t)(rowBase + rr) * 1024 + k0 + c];
        }
#pragma unroll
        for (int i = 0; i < 25; i++) {
            int e = tid + i * 256; int j = e >> 6, c = e & 63;
            sW[j][c] = W1[(size_t)j * 1024 + k0 + c];
        }
        __syncthreads();
#pragma unroll 8
        for (int k = 0; k < 64; k++) {
            float sv = sS[r][k];
#pragma unroll
            for (int j = 0; j < 25; j++) acc[j] += sv * sW[cs + j][k];
        }
        __syncthreads();
    }
#pragma unroll
    for (int j = 0; j < 25; j++) {
        float v = acc[j];
        g_x1[(size_t)(rowBase + r) * 100 + cs + j] = (v > 0.f) ? v : 0.2f * v;
    }
}

__global__ void mlp2_k(const float* __restrict__ W2) {
    int gw = (blockIdx.x * blockDim.x + threadIdx.x) >> 5;
    int lane = threadIdx.x & 31;
    if (gw >= BATCH * 100) return;
    int b = gw / 100, j = gw % 100;
    const float* xrow = g_x1 + (size_t)b * 100;
    const float* wrow = W2 + (size_t)j * 100;
    float acc = 0.f;
    for (int t = lane; t < 100; t += 32) acc += xrow[t] * wrow[t];
#pragma unroll
    for (int o = 16; o; o >>= 1) acc += __shfl_xor_sync(0xffffffffu, acc, o);
    if (lane == 0) g_x2[b * 100 + j] = (acc > 0.f) ? acc : 0.2f * acc;
}

__global__ void mlp3_k(const float* __restrict__ W3, float* __restrict__ out) {
    int gw = (blockIdx.x * blockDim.x + threadIdx.x) >> 5;
    int lane = threadIdx.x & 31;
    if (gw >= BATCH) return;
    const float* xrow = g_x2 + (size_t)gw * 100;
    float acc = 0.f;
    for (int t = lane; t < 100; t += 32) acc += xrow[t] * W3[t];
#pragma unroll
    for (int o = 16; o; o >>= 1) acc += __shfl_xor_sync(0xffffffffu, acc, o);
    if (lane == 0) out[gw] = acc;
}

// ======= launch =======
extern "C" void kernel_launch(void* const* d_in, const int* in_sizes, int n_in,
                              void* d_out, int out_size) {
    (void)in_sizes; (void)n_in; (void)out_size;
    const int*   dots    = (const int*)d_in[0];
    const float* w_each  = (const float*)d_in[1];
    const float* w_not   = (const float*)d_in[2];
    const float* w_not2  = (const float*)d_in[3];
    const float* w_empty = (const float*)d_in[4];
    const float* W1      = (const float*)d_in[5];
    const float* W2      = (const float*)d_in[6];
    const float* W3      = (const float*)d_in[7];
    float* out = (float*)d_out;

    const int SMEM = 3 * STAGEB;   // 98304
    cudaFuncSetAttribute(mma_gemm_k, cudaFuncAttributeMaxDynamicSharedMemorySize, SMEM);

    build_B_k<<<(CELLS*CELLS + 255)/256, 256>>>(w_each, w_not, w_not2, w_empty);
    build_masks_k<<<(KSTRIDE + 255)/256, 256>>>(dots);

    mma_gemm_k<<<dim3(8, 32),   256, SMEM>>>(0);   // E
    mma_gemm_k<<<dim3(16, 128), 256, SMEM>>>(1);   // Aea(masked) + P

    init_k<<<(KSTRIDE + 255)/256, 256>>>();

    for (int d = 0; d < 4; d++) {
        mma_gemm_k<<<dim3(8, 128), 256, SMEM>>>(3);   // D (interleaved 3-pass, masked)
        update_k<<<(KSTRIDE + 255)/256, 256>>>(d < 3 ? 1 : 0);
    }

    mlp1_k<<<BATCH/64, 256>>>(W1);
    {
        long nw = (long)BATCH * 100 * 32;
        mlp2_k<<<(unsigned)((nw + 255)/256), 256>>>(W2);
        long nw3 = (long)BATCH * 32;
        mlp3_k<<<(unsigned)((nw3 + 255)/256), 256>>>(W3, out);
    }
}